// round 6
// baseline (speedup 1.0000x reference)
#include <cuda_runtime.h>
#include <cstdint>
#include <cstddef>

// ---------------------------------------------------------------------------
// Problem constants: B=4, NQ=NK=4096, D=256
// Output layout (reference returns (h, attn)): d_out = [ h: 4*4096*256 | attn: 4*4096*4096 ]
// ---------------------------------------------------------------------------

#define BM 128
#define BN 128
#define BK 16
#define NTHREADS 256

// Scratch (device globals: allocation inside kernel_launch is forbidden)
__device__ float g_q [4 * 4096 * 256];
__device__ float g_k [4 * 4096 * 256];
__device__ float g_v [4 * 4096 * 256];
__device__ float g_t0[4 * 4096 * 256];
__device__ float g_t1[4 * 4096 * 256];

// ---------------------------------------------------------------------------
// packed f32x2 helpers (full-rate fp32 path on sm_103a; only reachable via PTX)
// ---------------------------------------------------------------------------
static __device__ __forceinline__ unsigned long long pack2(float lo, float hi) {
    unsigned long long r;
    asm("mov.b64 %0, {%1, %2};" : "=l"(r)
        : "r"(__float_as_uint(lo)), "r"(__float_as_uint(hi)));
    return r;
}
static __device__ __forceinline__ void fma2(unsigned long long& d,
                                            unsigned long long a,
                                            unsigned long long b) {
    asm("fma.rn.f32x2 %0, %1, %2, %0;" : "+l"(d) : "l"(a), "l"(b));
}
static __device__ __forceinline__ void unpack2(unsigned long long v, float& lo, float& hi) {
    unsigned int l, h;
    asm("mov.b64 {%0, %1}, %2;" : "=r"(l), "=r"(h) : "l"(v));
    lo = __uint_as_float(l);
    hi = __uint_as_float(h);
}

// ---------------------------------------------------------------------------
// Shared 128x128 register-tile micro-kernel (8x8 per thread, f32x2 packed).
// Thread mapping: warp = tid/32 -> (warp&3)*32 rows, (warp>>2)*64 cols.
// lane: ly=lane>>3 (8-row group), lx=lane&7 (4-col chunk; 2nd chunk at +32).
// Conflict-free: A reads are quarter-warp broadcasts; B reads cover 128B/phase.
// ---------------------------------------------------------------------------
static __device__ __forceinline__ void mma_ktile(
    const float (*As)[BM + 4], const float (*Bs)[BN + 4],
    int tm, int tn, unsigned long long acc[8][4])
{
#pragma unroll
    for (int kk = 0; kk < BK; kk++) {
        const float4 av0 = *(const float4*)&As[kk][tm];
        const float4 av1 = *(const float4*)&As[kk][tm + 4];
        const float4 bv0 = *(const float4*)&Bs[kk][tn];
        const float4 bv1 = *(const float4*)&Bs[kk][tn + 32];
        const unsigned long long b0 = pack2(bv0.x, bv0.y);
        const unsigned long long b1 = pack2(bv0.z, bv0.w);
        const unsigned long long b2 = pack2(bv1.x, bv1.y);
        const unsigned long long b3 = pack2(bv1.z, bv1.w);
        const float a[8] = {av0.x, av0.y, av0.z, av0.w,
                            av1.x, av1.y, av1.z, av1.w};
#pragma unroll
        for (int i = 0; i < 8; i++) {
            const unsigned long long aa = pack2(a[i], a[i]);
            fma2(acc[i][0], aa, b0);
            fma2(acc[i][1], aa, b1);
            fma2(acc[i][2], aa, b2);
            fma2(acc[i][3], aa, b3);
        }
    }
}

static __device__ __forceinline__ void epilogue(
    float* __restrict__ C, int N, const float* __restrict__ bias,
    int m0, int n0, int tm, int tn,
    unsigned long long acc[8][4], float alpha, int relu)
{
    float bb[8] = {0.f, 0.f, 0.f, 0.f, 0.f, 0.f, 0.f, 0.f};
    if (bias) {
        const float4 q0 = *(const float4*)(bias + n0 + tn);
        const float4 q1 = *(const float4*)(bias + n0 + tn + 32);
        bb[0] = q0.x; bb[1] = q0.y; bb[2] = q0.z; bb[3] = q0.w;
        bb[4] = q1.x; bb[5] = q1.y; bb[6] = q1.z; bb[7] = q1.w;
    }
#pragma unroll
    for (int i = 0; i < 8; i++) {
        float r[8];
        unpack2(acc[i][0], r[0], r[1]);
        unpack2(acc[i][1], r[2], r[3]);
        unpack2(acc[i][2], r[4], r[5]);
        unpack2(acc[i][3], r[6], r[7]);
#pragma unroll
        for (int j = 0; j < 8; j++) {
            r[j] = alpha * r[j] + bb[j];
            if (relu) r[j] = fmaxf(r[j], 0.0f);
        }
        float* crow = C + (size_t)(m0 + tm + i) * (size_t)N + (n0 + tn);
        float4 o0, o1;
        o0.x = r[0]; o0.y = r[1]; o0.z = r[2]; o0.w = r[3];
        o1.x = r[4]; o1.y = r[5]; o1.z = r[6]; o1.w = r[7];
        *(float4*)(crow)      = o0;
        *(float4*)(crow + 32) = o1;
    }
}

// ---------------------------------------------------------------------------
// NT GEMM: C[M,N] = alpha * A[M,K] * B[N,K]^T + bias  (+relu)
// Used for: q/k/v projections, QK^T scores, MLP layers.
// Requires M%128==0, N%128==0, K%16==0 (holds for all shapes here).
// ---------------------------------------------------------------------------
__global__ void __launch_bounds__(NTHREADS, 2) gemm_nt(
    const float* __restrict__ A, const float* __restrict__ B,
    const float* __restrict__ bias, float* __restrict__ C,
    int M, int N, int K,
    long long sA, long long sB, long long sC,
    float alpha, int relu)
{
    A += (size_t)blockIdx.z * (size_t)sA;
    B += (size_t)blockIdx.z * (size_t)sB;
    C += (size_t)blockIdx.z * (size_t)sC;
    const int m0 = blockIdx.y * BM;
    const int n0 = blockIdx.x * BN;

    __shared__ float As[BK][BM + 4];
    __shared__ float Bs[BK][BN + 4];

    const int tid  = threadIdx.x;
    const int lrow = tid >> 2;          // 0..63
    const int lcol = (tid & 3) << 2;    // 0,4,8,12
    const int warp = tid >> 5, lane = tid & 31;
    const int tm = (warp & 3) * 32 + (lane >> 3) * 8;
    const int tn = (warp >> 2) * 64 + (lane & 7) * 4;

    unsigned long long acc[8][4];
#pragma unroll
    for (int i = 0; i < 8; i++)
#pragma unroll
        for (int j = 0; j < 4; j++) acc[i][j] = 0ull;

    const float* Ar0 = A + (size_t)(m0 + lrow)      * (size_t)K + lcol;
    const float* Ar1 = A + (size_t)(m0 + lrow + 64) * (size_t)K + lcol;
    const float* Br0 = B + (size_t)(n0 + lrow)      * (size_t)K + lcol;
    const float* Br1 = B + (size_t)(n0 + lrow + 64) * (size_t)K + lcol;

    for (int k0 = 0; k0 < K; k0 += BK) {
        const float4 a0 = *(const float4*)(Ar0 + k0);
        const float4 a1 = *(const float4*)(Ar1 + k0);
        const float4 b0 = *(const float4*)(Br0 + k0);
        const float4 b1 = *(const float4*)(Br1 + k0);
        __syncthreads();
        As[lcol + 0][lrow] = a0.x; As[lcol + 1][lrow] = a0.y;
        As[lcol + 2][lrow] = a0.z; As[lcol + 3][lrow] = a0.w;
        As[lcol + 0][lrow + 64] = a1.x; As[lcol + 1][lrow + 64] = a1.y;
        As[lcol + 2][lrow + 64] = a1.z; As[lcol + 3][lrow + 64] = a1.w;
        Bs[lcol + 0][lrow] = b0.x; Bs[lcol + 1][lrow] = b0.y;
        Bs[lcol + 2][lrow] = b0.z; Bs[lcol + 3][lrow] = b0.w;
        Bs[lcol + 0][lrow + 64] = b1.x; Bs[lcol + 1][lrow + 64] = b1.y;
        Bs[lcol + 2][lrow + 64] = b1.z; Bs[lcol + 3][lrow + 64] = b1.w;
        __syncthreads();
        mma_ktile(As, Bs, tm, tn, acc);
    }
    epilogue(C, N, bias, m0, n0, tm, tn, acc, alpha, relu);
}

// ---------------------------------------------------------------------------
// NN GEMM: C[M,N] = A[M,K] * B[K,N]   (used for out = attn @ V)
// ---------------------------------------------------------------------------
__global__ void __launch_bounds__(NTHREADS, 2) gemm_nn(
    const float* __restrict__ A, const float* __restrict__ B,
    float* __restrict__ C,
    int M, int N, int K,
    long long sA, long long sB, long long sC)
{
    A += (size_t)blockIdx.z * (size_t)sA;
    B += (size_t)blockIdx.z * (size_t)sB;
    C += (size_t)blockIdx.z * (size_t)sC;
    const int m0 = blockIdx.y * BM;
    const int n0 = blockIdx.x * BN;

    __shared__ float As[BK][BM + 4];
    __shared__ float Bs[BK][BN + 4];

    const int tid  = threadIdx.x;
    const int lrow = tid >> 2;          // A-tile: 0..63
    const int lcol = (tid & 3) << 2;
    const int bR   = tid >> 5;          // B-tile: rows 0..7 (+8)
    const int bC   = (tid & 31) << 2;   // cols 0..124
    const int warp = tid >> 5, lane = tid & 31;
    const int tm = (warp & 3) * 32 + (lane >> 3) * 8;
    const int tn = (warp >> 2) * 64 + (lane & 7) * 4;

    unsigned long long acc[8][4];
#pragma unroll
    for (int i = 0; i < 8; i++)
#pragma unroll
        for (int j = 0; j < 4; j++) acc[i][j] = 0ull;

    const float* Ar0 = A + (size_t)(m0 + lrow)      * (size_t)K + lcol;
    const float* Ar1 = A + (size_t)(m0 + lrow + 64) * (size_t)K + lcol;

    for (int k0 = 0; k0 < K; k0 += BK) {
        const float4 a0 = *(const float4*)(Ar0 + k0);
        const float4 a1 = *(const float4*)(Ar1 + k0);
        const float4 b0 = *(const float4*)(B + (size_t)(k0 + bR)     * (size_t)N + n0 + bC);
        const float4 b1 = *(const float4*)(B + (size_t)(k0 + bR + 8) * (size_t)N + n0 + bC);
        __syncthreads();
        As[lcol + 0][lrow] = a0.x; As[lcol + 1][lrow] = a0.y;
        As[lcol + 2][lrow] = a0.z; As[lcol + 3][lrow] = a0.w;
        As[lcol + 0][lrow + 64] = a1.x; As[lcol + 1][lrow + 64] = a1.y;
        As[lcol + 2][lrow + 64] = a1.z; As[lcol + 3][lrow + 64] = a1.w;
        *(float4*)&Bs[bR][bC]     = b0;
        *(float4*)&Bs[bR + 8][bC] = b1;
        __syncthreads();
        mma_ktile(As, Bs, tm, tn, acc);
    }
    epilogue(C, N, nullptr, m0, n0, tm, tn, acc, 1.0f, 0);
}

// ---------------------------------------------------------------------------
// Row softmax in place over attn[16384][4096]. One CTA per row, 16 vals/thread.
// ---------------------------------------------------------------------------
static __device__ __forceinline__ float warpMax(float v) {
#pragma unroll
    for (int o = 16; o > 0; o >>= 1) v = fmaxf(v, __shfl_xor_sync(0xffffffffu, v, o));
    return v;
}
static __device__ __forceinline__ float warpSum(float v) {
#pragma unroll
    for (int o = 16; o > 0; o >>= 1) v += __shfl_xor_sync(0xffffffffu, v, o);
    return v;
}

__global__ void __launch_bounds__(256) softmax_rows(float* __restrict__ attn)
{
    __shared__ float red[8];
    __shared__ float bcast;
    const size_t row = blockIdx.x;
    float* p = attn + row * 4096;
    const int tid = threadIdx.x;

    float v[16];
#pragma unroll
    for (int i = 0; i < 16; i++) v[i] = p[tid + i * 256];

    float m = v[0];
#pragma unroll
    for (int i = 1; i < 16; i++) m = fmaxf(m, v[i]);
    m = warpMax(m);
    if ((tid & 31) == 0) red[tid >> 5] = m;
    __syncthreads();
    if (tid < 32) {
        float t = (tid < 8) ? red[tid] : -3.4e38f;
        t = warpMax(t);
        if (tid == 0) bcast = t;
    }
    __syncthreads();
    m = bcast;

    float s = 0.0f;
#pragma unroll
    for (int i = 0; i < 16; i++) { v[i] = __expf(v[i] - m); s += v[i]; }
    s = warpSum(s);
    __syncthreads();                 // red reuse
    if ((tid & 31) == 0) red[tid >> 5] = s;
    __syncthreads();
    if (tid < 32) {
        float t = (tid < 8) ? red[tid] : 0.0f;
        t = warpSum(t);
        if (tid == 0) bcast = t;
    }
    __syncthreads();
    const float inv = 1.0f / bcast;
#pragma unroll
    for (int i = 0; i < 16; i++) p[tid + i * 256] = v[i] * inv;
}

// ---------------------------------------------------------------------------
// Host launcher (graph-capturable: kernel launches only)
// ---------------------------------------------------------------------------
extern "C" void kernel_launch(void* const* d_in, const int* in_sizes, int n_in,
                              void* d_out, int out_size)
{
    (void)in_sizes; (void)n_in; (void)out_size;
    const float* x     = (const float*)d_in[0];
    const float* query = (const float*)d_in[1];
    const float* Wq = (const float*)d_in[2];  const float* bq = (const float*)d_in[3];
    const float* Wk = (const float*)d_in[4];  const float* bk = (const float*)d_in[5];
    const float* Wv = (const float*)d_in[6];  const float* bv = (const float*)d_in[7];
    const float* W1 = (const float*)d_in[8];  const float* b1 = (const float*)d_in[9];
    const float* W2 = (const float*)d_in[10]; const float* b2 = (const float*)d_in[11];
    const float* W3 = (const float*)d_in[12]; const float* b3 = (const float*)d_in[13];

    float* outp = (float*)d_out;
    float* hout = outp;                                    // [4,4096,256]
    float* attn = outp + (size_t)4 * 4096 * 256;           // [4,4096,4096]

    float *q, *k, *v, *t0, *t1;
    cudaGetSymbolAddress((void**)&q,  g_q);
    cudaGetSymbolAddress((void**)&k,  g_k);
    cudaGetSymbolAddress((void**)&v,  g_v);
    cudaGetSymbolAddress((void**)&t0, g_t0);
    cudaGetSymbolAddress((void**)&t1, g_t1);

    const int Mtot = 4 * 4096;   // flattened (B, NQ)
    const int D = 256;
    const int S = 4096;
    const dim3 blk(NTHREADS);
    const dim3 gLin(D / BN, Mtot / BM, 1);      // (2,128,1)

    // q/k/v projections: y = x @ W^T + b
    gemm_nt<<<gLin, blk>>>(query, Wq, bq, q, Mtot, D, D, 0, 0, 0, 1.0f, 0);
    gemm_nt<<<gLin, blk>>>(x,     Wk, bk, k, Mtot, D, D, 0, 0, 0, 1.0f, 0);
    gemm_nt<<<gLin, blk>>>(x,     Wv, bv, v, Mtot, D, D, 0, 0, 0, 1.0f, 0);

    // scores = (q @ k^T) * 1/sqrt(D) -> written straight into attn output slot
    const dim3 gScore(S / BN, S / BM, 4);       // (32,32,4)
    gemm_nt<<<gScore, blk>>>(q, k, nullptr, attn, S, S, D,
                             (long long)S * D, (long long)S * D,
                             (long long)S * S, 0.0625f, 0);

    // softmax rows, in place
    softmax_rows<<<Mtot, blk>>>(attn);

    // out = attn @ v
    const dim3 gAV(D / BN, S / BM, 4);          // (2,32,4)
    gemm_nn<<<gAV, blk>>>(attn, v, t0, S, D, S,
                          (long long)S * S, (long long)S * D, (long long)S * D);

    // MLP: three relu(linear) layers, last writes h output
    gemm_nt<<<gLin, blk>>>(t0, W1, b1, t1,   Mtot, D, D, 0, 0, 0, 1.0f, 1);
    gemm_nt<<<gLin, blk>>>(t1, W2, b2, t0,   Mtot, D, D, 0, 0, 0, 1.0f, 1);
    gemm_nt<<<gLin, blk>>>(t0, W3, b3, hout, Mtot, D, D, 0, 0, 0, 1.0f, 1);
}

// round 7
// speedup vs baseline: 1.0025x; 1.0025x over previous
#include <cuda_runtime.h>
#include <cstdint>
#include <cstddef>

// ---------------------------------------------------------------------------
// Problem constants: B=4, NQ=NK=4096, D=256
// Output layout (reference returns (h, attn)): d_out = [ h: 4*4096*256 | attn: 4*4096*4096 ]
// ---------------------------------------------------------------------------

#define BM 128
#define BN 128
#define BK 16
#define NTHREADS 256

// Scratch (device globals: allocation inside kernel_launch is forbidden)
__device__ float g_q [4 * 4096 * 256];
__device__ float g_k [4 * 4096 * 256];
__device__ float g_v [4 * 4096 * 256];
__device__ float g_t0[4 * 4096 * 256];
__device__ float g_t1[4 * 4096 * 256];

// ---------------------------------------------------------------------------
// packed f32x2 helpers (full-rate fp32 path on sm_103a; only reachable via PTX)
// ---------------------------------------------------------------------------
static __device__ __forceinline__ unsigned long long pack2(float lo, float hi) {
    unsigned long long r;
    asm("mov.b64 %0, {%1, %2};" : "=l"(r)
        : "r"(__float_as_uint(lo)), "r"(__float_as_uint(hi)));
    return r;
}
static __device__ __forceinline__ void fma2(unsigned long long& d,
                                            unsigned long long a,
                                            unsigned long long b) {
    asm("fma.rn.f32x2 %0, %1, %2, %0;" : "+l"(d) : "l"(a), "l"(b));
}
static __device__ __forceinline__ void unpack2(unsigned long long v, float& lo, float& hi) {
    unsigned int l, h;
    asm("mov.b64 {%0, %1}, %2;" : "=r"(l), "=r"(h) : "l"(v));
    lo = __uint_as_float(l);
    hi = __uint_as_float(h);
}

// ---------------------------------------------------------------------------
// Shared 128x128 register-tile micro-kernel (8x8 per thread, f32x2 packed).
// Thread mapping: warp = tid/32 -> (warp&3)*32 rows, (warp>>2)*64 cols.
// lane: ly=lane>>3 (8-row group), lx=lane&7 (4-col chunk; 2nd chunk at +32).
// Conflict-free: A reads are quarter-warp broadcasts; B reads cover 128B/phase.
// ---------------------------------------------------------------------------
static __device__ __forceinline__ void mma_ktile(
    const float (*As)[BM + 4], const float (*Bs)[BN + 4],
    int tm, int tn, unsigned long long acc[8][4])
{
#pragma unroll
    for (int kk = 0; kk < BK; kk++) {
        const float4 av0 = *(const float4*)&As[kk][tm];
        const float4 av1 = *(const float4*)&As[kk][tm + 4];
        const float4 bv0 = *(const float4*)&Bs[kk][tn];
        const float4 bv1 = *(const float4*)&Bs[kk][tn + 32];
        const unsigned long long b0 = pack2(bv0.x, bv0.y);
        const unsigned long long b1 = pack2(bv0.z, bv0.w);
        const unsigned long long b2 = pack2(bv1.x, bv1.y);
        const unsigned long long b3 = pack2(bv1.z, bv1.w);
        const float a[8] = {av0.x, av0.y, av0.z, av0.w,
                            av1.x, av1.y, av1.z, av1.w};
#pragma unroll
        for (int i = 0; i < 8; i++) {
            const unsigned long long aa = pack2(a[i], a[i]);
            fma2(acc[i][0], aa, b0);
            fma2(acc[i][1], aa, b1);
            fma2(acc[i][2], aa, b2);
            fma2(acc[i][3], aa, b3);
        }
    }
}

static __device__ __forceinline__ void epilogue(
    float* __restrict__ C, int N, const float* __restrict__ bias,
    int m0, int n0, int tm, int tn,
    unsigned long long acc[8][4], float alpha, int relu)
{
    float bb[8] = {0.f, 0.f, 0.f, 0.f, 0.f, 0.f, 0.f, 0.f};
    if (bias) {
        const float4 q0 = *(const float4*)(bias + n0 + tn);
        const float4 q1 = *(const float4*)(bias + n0 + tn + 32);
        bb[0] = q0.x; bb[1] = q0.y; bb[2] = q0.z; bb[3] = q0.w;
        bb[4] = q1.x; bb[5] = q1.y; bb[6] = q1.z; bb[7] = q1.w;
    }
#pragma unroll
    for (int i = 0; i < 8; i++) {
        float r[8];
        unpack2(acc[i][0], r[0], r[1]);
        unpack2(acc[i][1], r[2], r[3]);
        unpack2(acc[i][2], r[4], r[5]);
        unpack2(acc[i][3], r[6], r[7]);
#pragma unroll
        for (int j = 0; j < 8; j++) {
            r[j] = alpha * r[j] + bb[j];
            if (relu) r[j] = fmaxf(r[j], 0.0f);
        }
        float* crow = C + (size_t)(m0 + tm + i) * (size_t)N + (n0 + tn);
        float4 o0, o1;
        o0.x = r[0]; o0.y = r[1]; o0.z = r[2]; o0.w = r[3];
        o1.x = r[4]; o1.y = r[5]; o1.z = r[6]; o1.w = r[7];
        *(float4*)(crow)      = o0;
        *(float4*)(crow + 32) = o1;
    }
}

// ---------------------------------------------------------------------------
// NT GEMM: C[M,N] = alpha * A[M,K] * B[N,K]^T + bias  (+relu)
// Used for: q/k/v projections, QK^T scores, MLP layers.
// Requires M%128==0, N%128==0, K%16==0 (holds for all shapes here).
// ---------------------------------------------------------------------------
__global__ void __launch_bounds__(NTHREADS, 2) gemm_nt(
    const float* __restrict__ A, const float* __restrict__ B,
    const float* __restrict__ bias, float* __restrict__ C,
    int M, int N, int K,
    long long sA, long long sB, long long sC,
    float alpha, int relu)
{
    A += (size_t)blockIdx.z * (size_t)sA;
    B += (size_t)blockIdx.z * (size_t)sB;
    C += (size_t)blockIdx.z * (size_t)sC;
    const int m0 = blockIdx.y * BM;
    const int n0 = blockIdx.x * BN;

    __shared__ float As[BK][BM + 4];
    __shared__ float Bs[BK][BN + 4];

    const int tid  = threadIdx.x;
    const int lrow = tid >> 2;          // 0..63
    const int lcol = (tid & 3) << 2;    // 0,4,8,12
    const int warp = tid >> 5, lane = tid & 31;
    const int tm = (warp & 3) * 32 + (lane >> 3) * 8;
    const int tn = (warp >> 2) * 64 + (lane & 7) * 4;

    unsigned long long acc[8][4];
#pragma unroll
    for (int i = 0; i < 8; i++)
#pragma unroll
        for (int j = 0; j < 4; j++) acc[i][j] = 0ull;

    const float* Ar0 = A + (size_t)(m0 + lrow)      * (size_t)K + lcol;
    const float* Ar1 = A + (size_t)(m0 + lrow + 64) * (size_t)K + lcol;
    const float* Br0 = B + (size_t)(n0 + lrow)      * (size_t)K + lcol;
    const float* Br1 = B + (size_t)(n0 + lrow + 64) * (size_t)K + lcol;

    for (int k0 = 0; k0 < K; k0 += BK) {
        const float4 a0 = *(const float4*)(Ar0 + k0);
        const float4 a1 = *(const float4*)(Ar1 + k0);
        const float4 b0 = *(const float4*)(Br0 + k0);
        const float4 b1 = *(const float4*)(Br1 + k0);
        __syncthreads();
        As[lcol + 0][lrow] = a0.x; As[lcol + 1][lrow] = a0.y;
        As[lcol + 2][lrow] = a0.z; As[lcol + 3][lrow] = a0.w;
        As[lcol + 0][lrow + 64] = a1.x; As[lcol + 1][lrow + 64] = a1.y;
        As[lcol + 2][lrow + 64] = a1.z; As[lcol + 3][lrow + 64] = a1.w;
        Bs[lcol + 0][lrow] = b0.x; Bs[lcol + 1][lrow] = b0.y;
        Bs[lcol + 2][lrow] = b0.z; Bs[lcol + 3][lrow] = b0.w;
        Bs[lcol + 0][lrow + 64] = b1.x; Bs[lcol + 1][lrow + 64] = b1.y;
        Bs[lcol + 2][lrow + 64] = b1.z; Bs[lcol + 3][lrow + 64] = b1.w;
        __syncthreads();
        mma_ktile(As, Bs, tm, tn, acc);
    }
    epilogue(C, N, bias, m0, n0, tm, tn, acc, alpha, relu);
}

// ---------------------------------------------------------------------------
// NN GEMM: C[M,N] = A[M,K] * B[K,N]   (used for out = attn @ V)
// ---------------------------------------------------------------------------
__global__ void __launch_bounds__(NTHREADS, 2) gemm_nn(
    const float* __restrict__ A, const float* __restrict__ B,
    float* __restrict__ C,
    int M, int N, int K,
    long long sA, long long sB, long long sC)
{
    A += (size_t)blockIdx.z * (size_t)sA;
    B += (size_t)blockIdx.z * (size_t)sB;
    C += (size_t)blockIdx.z * (size_t)sC;
    const int m0 = blockIdx.y * BM;
    const int n0 = blockIdx.x * BN;

    __shared__ float As[BK][BM + 4];
    __shared__ float Bs[BK][BN + 4];

    const int tid  = threadIdx.x;
    const int lrow = tid >> 2;          // A-tile: 0..63
    const int lcol = (tid & 3) << 2;
    const int bR   = tid >> 5;          // B-tile: rows 0..7 (+8)
    const int bC   = (tid & 31) << 2;   // cols 0..124
    const int warp = tid >> 5, lane = tid & 31;
    const int tm = (warp & 3) * 32 + (lane >> 3) * 8;
    const int tn = (warp >> 2) * 64 + (lane & 7) * 4;

    unsigned long long acc[8][4];
#pragma unroll
    for (int i = 0; i < 8; i++)
#pragma unroll
        for (int j = 0; j < 4; j++) acc[i][j] = 0ull;

    const float* Ar0 = A + (size_t)(m0 + lrow)      * (size_t)K + lcol;
    const float* Ar1 = A + (size_t)(m0 + lrow + 64) * (size_t)K + lcol;

    for (int k0 = 0; k0 < K; k0 += BK) {
        const float4 a0 = *(const float4*)(Ar0 + k0);
        const float4 a1 = *(const float4*)(Ar1 + k0);
        const float4 b0 = *(const float4*)(B + (size_t)(k0 + bR)     * (size_t)N + n0 + bC);
        const float4 b1 = *(const float4*)(B + (size_t)(k0 + bR + 8) * (size_t)N + n0 + bC);
        __syncthreads();
        As[lcol + 0][lrow] = a0.x; As[lcol + 1][lrow] = a0.y;
        As[lcol + 2][lrow] = a0.z; As[lcol + 3][lrow] = a0.w;
        As[lcol + 0][lrow + 64] = a1.x; As[lcol + 1][lrow + 64] = a1.y;
        As[lcol + 2][lrow + 64] = a1.z; As[lcol + 3][lrow + 64] = a1.w;
        *(float4*)&Bs[bR][bC]     = b0;
        *(float4*)&Bs[bR + 8][bC] = b1;
        __syncthreads();
        mma_ktile(As, Bs, tm, tn, acc);
    }
    epilogue(C, N, nullptr, m0, n0, tm, tn, acc, 1.0f, 0);
}

// ---------------------------------------------------------------------------
// Row softmax in place over attn[16384][4096]. One CTA per row, 16 vals/thread.
// ---------------------------------------------------------------------------
static __device__ __forceinline__ float warpMax(float v) {
#pragma unroll
    for (int o = 16; o > 0; o >>= 1) v = fmaxf(v, __shfl_xor_sync(0xffffffffu, v, o));
    return v;
}
static __device__ __forceinline__ float warpSum(float v) {
#pragma unroll
    for (int o = 16; o > 0; o >>= 1) v += __shfl_xor_sync(0xffffffffu, v, o);
    return v;
}

__global__ void __launch_bounds__(256) softmax_rows(float* __restrict__ attn)
{
    __shared__ float red[8];
    __shared__ float bcast;
    const size_t row = blockIdx.x;
    float* p = attn + row * 4096;
    const int tid = threadIdx.x;

    float v[16];
#pragma unroll
    for (int i = 0; i < 16; i++) v[i] = p[tid + i * 256];

    float m = v[0];
#pragma unroll
    for (int i = 1; i < 16; i++) m = fmaxf(m, v[i]);
    m = warpMax(m);
    if ((tid & 31) == 0) red[tid >> 5] = m;
    __syncthreads();
    if (tid < 32) {
        float t = (tid < 8) ? red[tid] : -3.4e38f;
        t = warpMax(t);
        if (tid == 0) bcast = t;
    }
    __syncthreads();
    m = bcast;

    float s = 0.0f;
#pragma unroll
    for (int i = 0; i < 16; i++) { v[i] = __expf(v[i] - m); s += v[i]; }
    s = warpSum(s);
    __syncthreads();                 // red reuse
    if ((tid & 31) == 0) red[tid >> 5] = s;
    __syncthreads();
    if (tid < 32) {
        float t = (tid < 8) ? red[tid] : 0.0f;
        t = warpSum(t);
        if (tid == 0) bcast = t;
    }
    __syncthreads();
    const float inv = 1.0f / bcast;
#pragma unroll
    for (int i = 0; i < 16; i++) p[tid + i * 256] = v[i] * inv;
}

// ---------------------------------------------------------------------------
// Host launcher (graph-capturable: kernel launches only)
// ---------------------------------------------------------------------------
extern "C" void kernel_launch(void* const* d_in, const int* in_sizes, int n_in,
                              void* d_out, int out_size)
{
    (void)in_sizes; (void)n_in; (void)out_size;
    const float* x     = (const float*)d_in[0];
    const float* query = (const float*)d_in[1];
    const float* Wq = (const float*)d_in[2];  const float* bq = (const float*)d_in[3];
    const float* Wk = (const float*)d_in[4];  const float* bk = (const float*)d_in[5];
    const float* Wv = (const float*)d_in[6];  const float* bv = (const float*)d_in[7];
    const float* W1 = (const float*)d_in[8];  const float* b1 = (const float*)d_in[9];
    const float* W2 = (const float*)d_in[10]; const float* b2 = (const float*)d_in[11];
    const float* W3 = (const float*)d_in[12]; const float* b3 = (const float*)d_in[13];

    float* outp = (float*)d_out;
    float* hout = outp;                                    // [4,4096,256]
    float* attn = outp + (size_t)4 * 4096 * 256;           // [4,4096,4096]

    float *q, *k, *v, *t0, *t1;
    cudaGetSymbolAddress((void**)&q,  g_q);
    cudaGetSymbolAddress((void**)&k,  g_k);
    cudaGetSymbolAddress((void**)&v,  g_v);
    cudaGetSymbolAddress((void**)&t0, g_t0);
    cudaGetSymbolAddress((void**)&t1, g_t1);

    const int Mtot = 4 * 4096;   // flattened (B, NQ)
    const int D = 256;
    const int S = 4096;
    const dim3 blk(NTHREADS);
    const dim3 gLin(D / BN, Mtot / BM, 1);      // (2,128,1)

    // q/k/v projections: y = x @ W^T + b
    gemm_nt<<<gLin, blk>>>(query, Wq, bq, q, Mtot, D, D, 0, 0, 0, 1.0f, 0);
    gemm_nt<<<gLin, blk>>>(x,     Wk, bk, k, Mtot, D, D, 0, 0, 0, 1.0f, 0);
    gemm_nt<<<gLin, blk>>>(x,     Wv, bv, v, Mtot, D, D, 0, 0, 0, 1.0f, 0);

    // scores = (q @ k^T) * 1/sqrt(D) -> written straight into attn output slot
    const dim3 gScore(S / BN, S / BM, 4);       // (32,32,4)
    gemm_nt<<<gScore, blk>>>(q, k, nullptr, attn, S, S, D,
                             (long long)S * D, (long long)S * D,
                             (long long)S * S, 0.0625f, 0);

    // softmax rows, in place
    softmax_rows<<<Mtot, blk>>>(attn);

    // out = attn @ v
    const dim3 gAV(D / BN, S / BM, 4);          // (2,32,4)
    gemm_nn<<<gAV, blk>>>(attn, v, t0, S, D, S,
                          (long long)S * S, (long long)S * D, (long long)S * D);

    // MLP: three relu(linear) layers, last writes h output
    gemm_nt<<<gLin, blk>>>(t0, W1, b1, t1,   Mtot, D, D, 0, 0, 0, 1.0f, 1);
    gemm_nt<<<gLin, blk>>>(t1, W2, b2, t0,   Mtot, D, D, 0, 0, 0, 1.0f, 1);
    gemm_nt<<<gLin, blk>>>(t0, W3, b3, hout, Mtot, D, D, 0, 0, 0, 1.0f, 1);
}

// round 9
// speedup vs baseline: 1.6505x; 1.6465x over previous
#include <cuda_runtime.h>
#include <cuda_fp16.h>
#include <cstdint>
#include <cstddef>

// ---------------------------------------------------------------------------
// Problem constants: B=4, NQ=NK=4096, D=256
// d_out = [ h: 4*4096*256 | attn: 4*4096*4096 ]
// ---------------------------------------------------------------------------

#define BM 128
#define BN 128
#define BK 16
#define NTHREADS 256

// Scratch (device globals: allocation inside kernel_launch is forbidden)
__device__ float g_q [4 * 4096 * 256];
__device__ float g_k [4 * 4096 * 256];
__device__ float g_v [4 * 4096 * 256];
__device__ float g_t0[4 * 4096 * 256];
__device__ float g_t1[4 * 4096 * 256];   // V^T, then MLP temp

static __device__ __forceinline__ uint32_t smem_u32(const void* p) {
    uint32_t a;
    asm("{ .reg .u64 t; cvta.to.shared.u64 t, %1; cvt.u32.u64 %0, t; }"
        : "=r"(a) : "l"(p));
    return a;
}

// pack two fp32 -> fp16x2 (low = x, high = y)
static __device__ __forceinline__ uint32_t f2h2(float x, float y) {
    uint32_t r;
    asm("cvt.rn.f16x2.f32 %0, %1, %2;" : "=r"(r) : "f"(y), "f"(x));
    return r;
}

// ===========================================================================
// HMMA fp16 NT GEMM: C[M,N] = alpha * A[M,K] * B[N,K]^T   (fp32 in/out)
//   CTA tile 128x128, BK=32. 8 warps = 2(m) x 4(n); warp tile 64x32.
//   mma.sync m16n8k16 f16*f16+f32. Loaders convert fp32->fp16 at STS.
//   Smem rows = 32 fp16 + 8 pad = 80B (5 x 16B chunks): row stride 5 mod 8
//   in 16B banks -> conflict-free ldmatrix and STS.128.
//   Requires M%128==0, N%128==0, K%32==0.
// ===========================================================================
#define H_ROW   40          // fp16 per smem row (32 data + 8 pad)
#define H_MAT   (128 * H_ROW)        // 5120 halfs = 10240 B per matrix
#define H_BUF   (2 * H_MAT)          // A + B per buffer

__global__ void __launch_bounds__(256, 2) gemm_hmma_nt(
    const float* __restrict__ A, const float* __restrict__ B,
    float* __restrict__ C,
    int M, int N, int K,
    long long sA, long long sB, long long sC,
    float alpha)
{
    __shared__ __align__(16) __half sm[2 * H_BUF];   // 40960 B

    A += (size_t)blockIdx.z * (size_t)sA;
    B += (size_t)blockIdx.z * (size_t)sB;
    C += (size_t)blockIdx.z * (size_t)sC;
    const int m0 = blockIdx.y * 128;
    const int n0 = blockIdx.x * 128;
    const int tid = threadIdx.x;
    const int w = tid >> 5;
    const int l = tid & 31;

    // ---- loader mapping: thread covers row (w*16 + l&15), chunk pair (l>>4)
    const int ldr_row = w * 16 + (l & 15);
    const int ldr_cp  = l >> 4;                      // chunks {2cp, 2cp+1}
    const float* aG = A + (size_t)(m0 + ldr_row) * (size_t)K + ldr_cp * 16;
    const float* bG = B + (size_t)(n0 + ldr_row) * (size_t)K + ldr_cp * 16;

    uint32_t stA[2][4], stB[2][4];

    auto LDGC = [&]() {
#pragma unroll
        for (int j = 0; j < 2; j++) {
            float4 u = *(const float4*)(aG + j * 8);
            float4 v = *(const float4*)(aG + j * 8 + 4);
            stA[j][0] = f2h2(u.x, u.y); stA[j][1] = f2h2(u.z, u.w);
            stA[j][2] = f2h2(v.x, v.y); stA[j][3] = f2h2(v.z, v.w);
            u = *(const float4*)(bG + j * 8);
            v = *(const float4*)(bG + j * 8 + 4);
            stB[j][0] = f2h2(u.x, u.y); stB[j][1] = f2h2(u.z, u.w);
            stB[j][2] = f2h2(v.x, v.y); stB[j][3] = f2h2(v.z, v.w);
        }
    };
    auto STSC = [&](int buf) {
        __half* aS = sm + buf * H_BUF;
        __half* bS = aS + H_MAT;
#pragma unroll
        for (int j = 0; j < 2; j++) {
            const int c = 2 * ldr_cp + j;
            *(uint4*)(aS + ldr_row * H_ROW + c * 8) =
                make_uint4(stA[j][0], stA[j][1], stA[j][2], stA[j][3]);
            *(uint4*)(bS + ldr_row * H_ROW + c * 8) =
                make_uint4(stB[j][0], stB[j][1], stB[j][2], stB[j][3]);
        }
    };

    // ---- compute mapping
    const int wm = (w & 1) * 64;        // warp m-offset in tile
    const int wn = (w >> 1) * 32;       // warp n-offset in tile
    const uint32_t smem_base = smem_u32(sm);
    // ldmatrix per-lane byte offsets (within matrix, chunk s handled by +32*s)
    const uint32_t aoff = (uint32_t)((wm + (l & 15)) * 80 + (l >> 4) * 16);
    const uint32_t boff = (uint32_t)((wn + (l & 7)) * 80 + ((l >> 3) & 1) * 16);

    float acc[4][4][4];
#pragma unroll
    for (int i = 0; i < 4; i++)
#pragma unroll
        for (int j = 0; j < 4; j++)
#pragma unroll
            for (int q = 0; q < 4; q++) acc[i][j][q] = 0.0f;

    const int nch = K / 32;

    LDGC();
    STSC(0);
    __syncthreads();

    for (int c = 0; c < nch; c++) {
        const int buf = c & 1;
        if (c + 1 < nch) { aG += 32; bG += 32; LDGC(); }

        const uint32_t aB = smem_base + buf * (H_BUF * 2);      // bytes
        const uint32_t bB = aB + (H_MAT * 2);
#pragma unroll
        for (int s = 0; s < 2; s++) {
            uint32_t af[4][4];
#pragma unroll
            for (int ma = 0; ma < 4; ma++) {
                const uint32_t addr = aB + aoff + (uint32_t)(ma * 16 * 80 + s * 32);
                asm volatile(
                    "ldmatrix.sync.aligned.m8n8.x4.shared.b16 {%0,%1,%2,%3}, [%4];"
                    : "=r"(af[ma][0]), "=r"(af[ma][1]),
                      "=r"(af[ma][2]), "=r"(af[ma][3])
                    : "r"(addr));
            }
            uint32_t bf[4][2];
#pragma unroll
            for (int na = 0; na < 4; na++) {
                const uint32_t addr = bB + boff + (uint32_t)(na * 8 * 80 + s * 32);
                asm volatile(
                    "ldmatrix.sync.aligned.m8n8.x2.shared.b16 {%0,%1}, [%2];"
                    : "=r"(bf[na][0]), "=r"(bf[na][1])
                    : "r"(addr));
            }
#pragma unroll
            for (int ma = 0; ma < 4; ma++)
#pragma unroll
                for (int na = 0; na < 4; na++) {
                    asm volatile(
                        "mma.sync.aligned.m16n8k16.row.col.f32.f16.f16.f32 "
                        "{%0,%1,%2,%3}, {%4,%5,%6,%7}, {%8,%9}, {%0,%1,%2,%3};"
                        : "+f"(acc[ma][na][0]), "+f"(acc[ma][na][1]),
                          "+f"(acc[ma][na][2]), "+f"(acc[ma][na][3])
                        : "r"(af[ma][0]), "r"(af[ma][1]),
                          "r"(af[ma][2]), "r"(af[ma][3]),
                          "r"(bf[na][0]), "r"(bf[na][1]));
                }
        }
        if (c + 1 < nch) {
            STSC(buf ^ 1);
            __syncthreads();
        }
    }

    // ---- epilogue: c0,c1 -> (row, col..col+1); c2,c3 -> (row+8, ...)
    const int erow = m0 + wm + (l >> 2);
    const int ecol = n0 + wn + (l & 3) * 2;
#pragma unroll
    for (int ma = 0; ma < 4; ma++) {
        const int r = erow + ma * 16;
#pragma unroll
        for (int na = 0; na < 4; na++) {
            const int cc = ecol + na * 8;
            float2 lo, hi;
            lo.x = alpha * acc[ma][na][0];
            lo.y = alpha * acc[ma][na][1];
            hi.x = alpha * acc[ma][na][2];
            hi.y = alpha * acc[ma][na][3];
            *(float2*)(C + (size_t)r * (size_t)N + cc)       = lo;
            *(float2*)(C + (size_t)(r + 8) * (size_t)N + cc) = hi;
        }
    }
}

// ===========================================================================
// V transpose: vt[b][d][t] = v[b][t][d]   (4096 x 256 -> 256 x 4096 per batch)
// ===========================================================================
__global__ void __launch_bounds__(256) transpose256(
    const float* __restrict__ src, float* __restrict__ dst)
{
    __shared__ float t[32][33];
    const int b = blockIdx.z;
    const int k0 = blockIdx.x * 32, n0 = blockIdx.y * 32;
    const float* s = src + (size_t)b * 4096 * 256;
    float* d = dst + (size_t)b * 4096 * 256;
    const int tx = threadIdx.x & 31, ty = (threadIdx.x >> 5) * 4;
#pragma unroll
    for (int i = 0; i < 4; i++)
        t[ty + i][tx] = s[(size_t)(k0 + ty + i) * 256 + n0 + tx];
    __syncthreads();
#pragma unroll
    for (int i = 0; i < 4; i++)
        d[(size_t)(n0 + ty + i) * 4096 + k0 + tx] = t[tx][ty + i];
}

// ===========================================================================
// SIMT fp32 f32x2 GEMM (proven path) for the 6 small D=256 GEMMs
// ===========================================================================
static __device__ __forceinline__ unsigned long long pack2(float lo, float hi) {
    unsigned long long r;
    asm("mov.b64 %0, {%1, %2};" : "=l"(r)
        : "r"(__float_as_uint(lo)), "r"(__float_as_uint(hi)));
    return r;
}
static __device__ __forceinline__ void fma2(unsigned long long& d,
                                            unsigned long long a,
                                            unsigned long long b) {
    asm("fma.rn.f32x2 %0, %1, %2, %0;" : "+l"(d) : "l"(a), "l"(b));
}
static __device__ __forceinline__ void unpack2(unsigned long long v, float& lo, float& hi) {
    unsigned int l, h;
    asm("mov.b64 {%0, %1}, %2;" : "=r"(l), "=r"(h) : "l"(v));
    lo = __uint_as_float(l);
    hi = __uint_as_float(h);
}

static __device__ __forceinline__ void mma_ktile(
    const float (*As)[BM + 4], const float (*Bs)[BN + 4],
    int tm, int tn, unsigned long long acc[8][4])
{
#pragma unroll
    for (int kk = 0; kk < BK; kk++) {
        const float4 av0 = *(const float4*)&As[kk][tm];
        const float4 av1 = *(const float4*)&As[kk][tm + 4];
        const float4 bv0 = *(const float4*)&Bs[kk][tn];
        const float4 bv1 = *(const float4*)&Bs[kk][tn + 32];
        const unsigned long long b0 = pack2(bv0.x, bv0.y);
        const unsigned long long b1 = pack2(bv0.z, bv0.w);
        const unsigned long long b2 = pack2(bv1.x, bv1.y);
        const unsigned long long b3 = pack2(bv1.z, bv1.w);
        const float a[8] = {av0.x, av0.y, av0.z, av0.w,
                            av1.x, av1.y, av1.z, av1.w};
#pragma unroll
        for (int i = 0; i < 8; i++) {
            const unsigned long long aa = pack2(a[i], a[i]);
            fma2(acc[i][0], aa, b0);
            fma2(acc[i][1], aa, b1);
            fma2(acc[i][2], aa, b2);
            fma2(acc[i][3], aa, b3);
        }
    }
}

static __device__ __forceinline__ void epilogue(
    float* __restrict__ C, int N, const float* __restrict__ bias,
    int m0, int n0, int tm, int tn,
    unsigned long long acc[8][4], float alpha, int relu)
{
    float bb[8] = {0.f, 0.f, 0.f, 0.f, 0.f, 0.f, 0.f, 0.f};
    if (bias) {
        const float4 q0 = *(const float4*)(bias + n0 + tn);
        const float4 q1 = *(const float4*)(bias + n0 + tn + 32);
        bb[0] = q0.x; bb[1] = q0.y; bb[2] = q0.z; bb[3] = q0.w;
        bb[4] = q1.x; bb[5] = q1.y; bb[6] = q1.z; bb[7] = q1.w;
    }
#pragma unroll
    for (int i = 0; i < 8; i++) {
        float r[8];
        unpack2(acc[i][0], r[0], r[1]);
        unpack2(acc[i][1], r[2], r[3]);
        unpack2(acc[i][2], r[4], r[5]);
        unpack2(acc[i][3], r[6], r[7]);
#pragma unroll
        for (int j = 0; j < 8; j++) {
            r[j] = alpha * r[j] + bb[j];
            if (relu) r[j] = fmaxf(r[j], 0.0f);
        }
        float* crow = C + (size_t)(m0 + tm + i) * (size_t)N + (n0 + tn);
        float4 o0, o1;
        o0.x = r[0]; o0.y = r[1]; o0.z = r[2]; o0.w = r[3];
        o1.x = r[4]; o1.y = r[5]; o1.z = r[6]; o1.w = r[7];
        *(float4*)(crow)      = o0;
        *(float4*)(crow + 32) = o1;
    }
}

__global__ void __launch_bounds__(NTHREADS, 2) gemm_nt(
    const float* __restrict__ A, const float* __restrict__ B,
    const float* __restrict__ bias, float* __restrict__ C,
    int M, int N, int K,
    long long sA, long long sB, long long sC,
    float alpha, int relu)
{
    A += (size_t)blockIdx.z * (size_t)sA;
    B += (size_t)blockIdx.z * (size_t)sB;
    C += (size_t)blockIdx.z * (size_t)sC;
    const int m0 = blockIdx.y * BM;
    const int n0 = blockIdx.x * BN;

    __shared__ float As[BK][BM + 4];
    __shared__ float Bs[BK][BN + 4];

    const int tid  = threadIdx.x;
    const int lrow = tid >> 2;
    const int lcol = (tid & 3) << 2;
    const int warp = tid >> 5, lane = tid & 31;
    const int tm = (warp & 3) * 32 + (lane >> 3) * 8;
    const int tn = (warp >> 2) * 64 + (lane & 7) * 4;

    unsigned long long acc[8][4];
#pragma unroll
    for (int i = 0; i < 8; i++)
#pragma unroll
        for (int j = 0; j < 4; j++) acc[i][j] = 0ull;

    const float* Ar0 = A + (size_t)(m0 + lrow)      * (size_t)K + lcol;
    const float* Ar1 = A + (size_t)(m0 + lrow + 64) * (size_t)K + lcol;
    const float* Br0 = B + (size_t)(n0 + lrow)      * (size_t)K + lcol;
    const float* Br1 = B + (size_t)(n0 + lrow + 64) * (size_t)K + lcol;

    for (int k0 = 0; k0 < K; k0 += BK) {
        const float4 a0 = *(const float4*)(Ar0 + k0);
        const float4 a1 = *(const float4*)(Ar1 + k0);
        const float4 b0 = *(const float4*)(Br0 + k0);
        const float4 b1 = *(const float4*)(Br1 + k0);
        __syncthreads();
        As[lcol + 0][lrow] = a0.x; As[lcol + 1][lrow] = a0.y;
        As[lcol + 2][lrow] = a0.z; As[lcol + 3][lrow] = a0.w;
        As[lcol + 0][lrow + 64] = a1.x; As[lcol + 1][lrow + 64] = a1.y;
        As[lcol + 2][lrow + 64] = a1.z; As[lcol + 3][lrow + 64] = a1.w;
        Bs[lcol + 0][lrow] = b0.x; Bs[lcol + 1][lrow] = b0.y;
        Bs[lcol + 2][lrow] = b0.z; Bs[lcol + 3][lrow] = b0.w;
        Bs[lcol + 0][lrow + 64] = b1.x; Bs[lcol + 1][lrow + 64] = b1.y;
        Bs[lcol + 2][lrow + 64] = b1.z; Bs[lcol + 3][lrow + 64] = b1.w;
        __syncthreads();
        mma_ktile(As, Bs, tm, tn, acc);
    }
    epilogue(C, N, bias, m0, n0, tm, tn, acc, alpha, relu);
}

// ---------------------------------------------------------------------------
// Row softmax in place over attn[16384][4096].
// ---------------------------------------------------------------------------
static __device__ __forceinline__ float warpMax(float v) {
#pragma unroll
    for (int o = 16; o > 0; o >>= 1) v = fmaxf(v, __shfl_xor_sync(0xffffffffu, v, o));
    return v;
}
static __device__ __forceinline__ float warpSum(float v) {
#pragma unroll
    for (int o = 16; o > 0; o >>= 1) v += __shfl_xor_sync(0xffffffffu, v, o);
    return v;
}

__global__ void __launch_bounds__(256) softmax_rows(float* __restrict__ attn)
{
    __shared__ float red[8];
    __shared__ float bcast;
    const size_t row = blockIdx.x;
    float* p = attn + row * 4096;
    const int tid = threadIdx.x;

    float v[16];
#pragma unroll
    for (int i = 0; i < 16; i++) v[i] = p[tid + i * 256];

    float m = v[0];
#pragma unroll
    for (int i = 1; i < 16; i++) m = fmaxf(m, v[i]);
    m = warpMax(m);
    if ((tid & 31) == 0) red[tid >> 5] = m;
    __syncthreads();
    if (tid < 32) {
        float t = (tid < 8) ? red[tid] : -3.4e38f;
        t = warpMax(t);
        if (tid == 0) bcast = t;
    }
    __syncthreads();
    m = bcast;

    float s = 0.0f;
#pragma unroll
    for (int i = 0; i < 16; i++) { v[i] = __expf(v[i] - m); s += v[i]; }
    s = warpSum(s);
    __syncthreads();
    if ((tid & 31) == 0) red[tid >> 5] = s;
    __syncthreads();
    if (tid < 32) {
        float t = (tid < 8) ? red[tid] : 0.0f;
        t = warpSum(t);
        if (tid == 0) bcast = t;
    }
    __syncthreads();
    const float inv = 1.0f / bcast;
#pragma unroll
    for (int i = 0; i < 16; i++) p[tid + i * 256] = v[i] * inv;
}

// ---------------------------------------------------------------------------
// Host launcher (graph-capturable: kernel launches only)
// ---------------------------------------------------------------------------
extern "C" void kernel_launch(void* const* d_in, const int* in_sizes, int n_in,
                              void* d_out, int out_size)
{
    (void)in_sizes; (void)n_in; (void)out_size;
    const float* x     = (const float*)d_in[0];
    const float* query = (const float*)d_in[1];
    const float* Wq = (const float*)d_in[2];  const float* bq = (const float*)d_in[3];
    const float* Wk = (const float*)d_in[4];  const float* bk = (const float*)d_in[5];
    const float* Wv = (const float*)d_in[6];  const float* bv = (const float*)d_in[7];
    const float* W1 = (const float*)d_in[8];  const float* b1 = (const float*)d_in[9];
    const float* W2 = (const float*)d_in[10]; const float* b2 = (const float*)d_in[11];
    const float* W3 = (const float*)d_in[12]; const float* b3 = (const float*)d_in[13];

    float* outp = (float*)d_out;
    float* hout = outp;                                    // [4,4096,256]
    float* attn = outp + (size_t)4 * 4096 * 256;           // [4,4096,4096]

    float *q, *k, *v, *t0, *vt;
    cudaGetSymbolAddress((void**)&q,  g_q);
    cudaGetSymbolAddress((void**)&k,  g_k);
    cudaGetSymbolAddress((void**)&v,  g_v);
    cudaGetSymbolAddress((void**)&t0, g_t0);
    cudaGetSymbolAddress((void**)&vt, g_t1);               // V^T, then MLP temp

    const int Mtot = 4 * 4096;
    const int D = 256;
    const int S = 4096;
    const dim3 blk(NTHREADS);
    const dim3 gLin(D / BN, Mtot / BM, 1);

    // q/k/v projections (fp32 SIMT): y = x @ W^T + b
    gemm_nt<<<gLin, blk>>>(query, Wq, bq, q, Mtot, D, D, 0, 0, 0, 1.0f, 0);
    gemm_nt<<<gLin, blk>>>(x,     Wk, bk, k, Mtot, D, D, 0, 0, 0, 1.0f, 0);
    gemm_nt<<<gLin, blk>>>(x,     Wv, bv, v, Mtot, D, D, 0, 0, 0, 1.0f, 0);

    // V^T per batch (for tensor-core AV)
    transpose256<<<dim3(S / 32, D / 32, 4), 256>>>(v, vt);

    // scores = (q @ k^T) / sqrt(D) -> attn output slot  (HMMA fp16, fp32 acc)
    gemm_hmma_nt<<<dim3(S / 128, S / 128, 4), 256>>>(
        q, k, attn, S, S, D,
        (long long)S * D, (long long)S * D, (long long)S * S, 0.0625f);

    // softmax rows, in place (fp32)
    softmax_rows<<<Mtot, blk>>>(attn);

    // out = attn @ V = attn @ (V^T)^T  (HMMA fp16, fp32 acc)
    gemm_hmma_nt<<<dim3(D / 128, S / 128, 4), 256>>>(
        attn, vt, t0, S, D, S,
        (long long)S * S, (long long)D * S, (long long)S * D, 1.0f);

    // MLP (fp32 SIMT): three relu(linear) layers, last writes h output
    gemm_nt<<<gLin, blk>>>(t0, W1, b1, vt,   Mtot, D, D, 0, 0, 0, 1.0f, 1);
    gemm_nt<<<gLin, blk>>>(vt, W2, b2, t0,   Mtot, D, D, 0, 0, 0, 1.0f, 1);
    gemm_nt<<<gLin, blk>>>(t0, W3, b3, hout, Mtot, D, D, 0, 0, 0, 1.0f, 1);
}

// round 10
// speedup vs baseline: 1.8989x; 1.1505x over previous
#include <cuda_runtime.h>
#include <cuda_fp16.h>
#include <cstdint>
#include <cstddef>

// ---------------------------------------------------------------------------
// Problem constants: B=4, NQ=NK=4096, D=256
// d_out = [ h: 4*4096*256 | attn: 4*4096*4096 ]
// ---------------------------------------------------------------------------

// Scratch (device globals: allocation inside kernel_launch is forbidden)
__device__ float g_q [4 * 4096 * 256];
__device__ float g_k [4 * 4096 * 256];
__device__ float g_v [4 * 4096 * 256];
__device__ float g_t0[4 * 4096 * 256];
__device__ float g_t1[4 * 4096 * 256];   // V^T, then MLP temp

static __device__ __forceinline__ uint32_t smem_u32(const void* p) {
    uint32_t a;
    asm("{ .reg .u64 t; cvta.to.shared.u64 t, %1; cvt.u32.u64 %0, t; }"
        : "=r"(a) : "l"(p));
    return a;
}

// pack two fp32 -> fp16x2 (low = x, high = y)
static __device__ __forceinline__ uint32_t f2h2(float x, float y) {
    uint32_t r;
    asm("cvt.rn.f16x2.f32 %0, %1, %2;" : "=r"(r) : "f"(y), "f"(x));
    return r;
}

// ===========================================================================
// HMMA fp16 NT GEMM: C[M,N] = alpha * A[M,K] * B[N,K]^T (+bias, +relu)
//   fp32 in/out, fp16 MMA operands, fp32 accumulate.
//   CTA tile 128x128, BK=32. 8 warps = 2(m) x 4(n); warp tile 64x32.
//   Smem rows = 32 fp16 + 8 pad = 80B (5 x 16B): stride 5 mod 8 in 16B banks
//   -> conflict-free ldmatrix / STS.128 by construction.
//   Requires M%128==0, N%128==0, K%32==0.
// ===========================================================================
#define H_ROW   40                   // fp16 per smem row (32 data + 8 pad)
#define H_MAT   (128 * H_ROW)        // 5120 halfs = 10240 B per matrix
#define H_BUF   (2 * H_MAT)          // A + B per buffer

__global__ void __launch_bounds__(256, 2) gemm_hmma_nt(
    const float* __restrict__ A, const float* __restrict__ B,
    const float* __restrict__ bias, float* __restrict__ C,
    int M, int N, int K,
    long long sA, long long sB, long long sC,
    float alpha, int relu)
{
    __shared__ __align__(16) __half sm[2 * H_BUF];   // 40960 B

    A += (size_t)blockIdx.z * (size_t)sA;
    B += (size_t)blockIdx.z * (size_t)sB;
    C += (size_t)blockIdx.z * (size_t)sC;
    const int m0 = blockIdx.y * 128;
    const int n0 = blockIdx.x * 128;
    const int tid = threadIdx.x;
    const int w = tid >> 5;
    const int l = tid & 31;

    // ---- loader mapping: thread covers row (w*16 + l&15), chunk pair (l>>4)
    const int ldr_row = w * 16 + (l & 15);
    const int ldr_cp  = l >> 4;                      // chunks {2cp, 2cp+1}
    const float* aG = A + (size_t)(m0 + ldr_row) * (size_t)K + ldr_cp * 16;
    const float* bG = B + (size_t)(n0 + ldr_row) * (size_t)K + ldr_cp * 16;

    uint32_t stA[2][4], stB[2][4];

    auto LDGC = [&]() {
#pragma unroll
        for (int j = 0; j < 2; j++) {
            float4 u = *(const float4*)(aG + j * 8);
            float4 v = *(const float4*)(aG + j * 8 + 4);
            stA[j][0] = f2h2(u.x, u.y); stA[j][1] = f2h2(u.z, u.w);
            stA[j][2] = f2h2(v.x, v.y); stA[j][3] = f2h2(v.z, v.w);
            u = *(const float4*)(bG + j * 8);
            v = *(const float4*)(bG + j * 8 + 4);
            stB[j][0] = f2h2(u.x, u.y); stB[j][1] = f2h2(u.z, u.w);
            stB[j][2] = f2h2(v.x, v.y); stB[j][3] = f2h2(v.z, v.w);
        }
    };
    auto STSC = [&](int buf) {
        __half* aS = sm + buf * H_BUF;
        __half* bS = aS + H_MAT;
#pragma unroll
        for (int j = 0; j < 2; j++) {
            const int c = 2 * ldr_cp + j;
            *(uint4*)(aS + ldr_row * H_ROW + c * 8) =
                make_uint4(stA[j][0], stA[j][1], stA[j][2], stA[j][3]);
            *(uint4*)(bS + ldr_row * H_ROW + c * 8) =
                make_uint4(stB[j][0], stB[j][1], stB[j][2], stB[j][3]);
        }
    };

    // ---- compute mapping
    const int wm = (w & 1) * 64;        // warp m-offset in tile
    const int wn = (w >> 1) * 32;       // warp n-offset in tile
    const uint32_t smem_base = smem_u32(sm);
    const uint32_t aoff = (uint32_t)((wm + (l & 15)) * 80 + (l >> 4) * 16);
    const uint32_t boff = (uint32_t)((wn + (l & 7)) * 80 + ((l >> 3) & 1) * 16);

    float acc[4][4][4];
#pragma unroll
    for (int i = 0; i < 4; i++)
#pragma unroll
        for (int j = 0; j < 4; j++)
#pragma unroll
            for (int q = 0; q < 4; q++) acc[i][j][q] = 0.0f;

    const int nch = K / 32;

    LDGC();
    STSC(0);
    __syncthreads();

    for (int c = 0; c < nch; c++) {
        const int buf = c & 1;
        if (c + 1 < nch) { aG += 32; bG += 32; LDGC(); }

        const uint32_t aB = smem_base + buf * (H_BUF * 2);      // bytes
        const uint32_t bB = aB + (H_MAT * 2);
#pragma unroll
        for (int s = 0; s < 2; s++) {
            uint32_t af[4][4];
#pragma unroll
            for (int ma = 0; ma < 4; ma++) {
                const uint32_t addr = aB + aoff + (uint32_t)(ma * 16 * 80 + s * 32);
                asm volatile(
                    "ldmatrix.sync.aligned.m8n8.x4.shared.b16 {%0,%1,%2,%3}, [%4];"
                    : "=r"(af[ma][0]), "=r"(af[ma][1]),
                      "=r"(af[ma][2]), "=r"(af[ma][3])
                    : "r"(addr));
            }
            uint32_t bf[4][2];
#pragma unroll
            for (int na = 0; na < 4; na++) {
                const uint32_t addr = bB + boff + (uint32_t)(na * 8 * 80 + s * 32);
                asm volatile(
                    "ldmatrix.sync.aligned.m8n8.x2.shared.b16 {%0,%1}, [%2];"
                    : "=r"(bf[na][0]), "=r"(bf[na][1])
                    : "r"(addr));
            }
#pragma unroll
            for (int ma = 0; ma < 4; ma++)
#pragma unroll
                for (int na = 0; na < 4; na++) {
                    asm volatile(
                        "mma.sync.aligned.m16n8k16.row.col.f32.f16.f16.f32 "
                        "{%0,%1,%2,%3}, {%4,%5,%6,%7}, {%8,%9}, {%0,%1,%2,%3};"
                        : "+f"(acc[ma][na][0]), "+f"(acc[ma][na][1]),
                          "+f"(acc[ma][na][2]), "+f"(acc[ma][na][3])
                        : "r"(af[ma][0]), "r"(af[ma][1]),
                          "r"(af[ma][2]), "r"(af[ma][3]),
                          "r"(bf[na][0]), "r"(bf[na][1]));
                }
        }
        if (c + 1 < nch) {
            STSC(buf ^ 1);
            __syncthreads();
        }
    }

    // ---- epilogue: c0,c1 -> (row, col..col+1); c2,c3 -> (row+8, ...)
    const int erow = m0 + wm + (l >> 2);
    const int ecol = n0 + wn + (l & 3) * 2;
#pragma unroll
    for (int ma = 0; ma < 4; ma++) {
        const int r = erow + ma * 16;
#pragma unroll
        for (int na = 0; na < 4; na++) {
            const int cc = ecol + na * 8;
            float2 bb = make_float2(0.f, 0.f);
            if (bias) bb = *(const float2*)(bias + cc);
            float2 lo, hi;
            lo.x = alpha * acc[ma][na][0] + bb.x;
            lo.y = alpha * acc[ma][na][1] + bb.y;
            hi.x = alpha * acc[ma][na][2] + bb.x;
            hi.y = alpha * acc[ma][na][3] + bb.y;
            if (relu) {
                lo.x = fmaxf(lo.x, 0.f); lo.y = fmaxf(lo.y, 0.f);
                hi.x = fmaxf(hi.x, 0.f); hi.y = fmaxf(hi.y, 0.f);
            }
            *(float2*)(C + (size_t)r * (size_t)N + cc)       = lo;
            *(float2*)(C + (size_t)(r + 8) * (size_t)N + cc) = hi;
        }
    }
}

// ===========================================================================
// V transpose: vt[b][d][t] = v[b][t][d]   (4096 x 256 -> 256 x 4096 per batch)
// ===========================================================================
__global__ void __launch_bounds__(256) transpose256(
    const float* __restrict__ src, float* __restrict__ dst)
{
    __shared__ float t[32][33];
    const int b = blockIdx.z;
    const int k0 = blockIdx.x * 32, n0 = blockIdx.y * 32;
    const float* s = src + (size_t)b * 4096 * 256;
    float* d = dst + (size_t)b * 4096 * 256;
    const int tx = threadIdx.x & 31, ty = (threadIdx.x >> 5) * 4;
#pragma unroll
    for (int i = 0; i < 4; i++)
        t[ty + i][tx] = s[(size_t)(k0 + ty + i) * 256 + n0 + tx];
    __syncthreads();
#pragma unroll
    for (int i = 0; i < 4; i++)
        d[(size_t)(n0 + ty + i) * 4096 + k0 + tx] = t[tx][ty + i];
}

// ---------------------------------------------------------------------------
// Row softmax in place over attn[16384][4096].
// ---------------------------------------------------------------------------
static __device__ __forceinline__ float warpMax(float v) {
#pragma unroll
    for (int o = 16; o > 0; o >>= 1) v = fmaxf(v, __shfl_xor_sync(0xffffffffu, v, o));
    return v;
}
static __device__ __forceinline__ float warpSum(float v) {
#pragma unroll
    for (int o = 16; o > 0; o >>= 1) v += __shfl_xor_sync(0xffffffffu, v, o);
    return v;
}

__global__ void __launch_bounds__(256) softmax_rows(float* __restrict__ attn)
{
    __shared__ float red[8];
    __shared__ float bcast;
    const size_t row = blockIdx.x;
    float* p = attn + row * 4096;
    const int tid = threadIdx.x;

    float v[16];
#pragma unroll
    for (int i = 0; i < 16; i++) v[i] = p[tid + i * 256];

    float m = v[0];
#pragma unroll
    for (int i = 1; i < 16; i++) m = fmaxf(m, v[i]);
    m = warpMax(m);
    if ((tid & 31) == 0) red[tid >> 5] = m;
    __syncthreads();
    if (tid < 32) {
        float t = (tid < 8) ? red[tid] : -3.4e38f;
        t = warpMax(t);
        if (tid == 0) bcast = t;
    }
    __syncthreads();
    m = bcast;

    float s = 0.0f;
#pragma unroll
    for (int i = 0; i < 16; i++) { v[i] = __expf(v[i] - m); s += v[i]; }
    s = warpSum(s);
    __syncthreads();
    if ((tid & 31) == 0) red[tid >> 5] = s;
    __syncthreads();
    if (tid < 32) {
        float t = (tid < 8) ? red[tid] : 0.0f;
        t = warpSum(t);
        if (tid == 0) bcast = t;
    }
    __syncthreads();
    const float inv = 1.0f / bcast;
#pragma unroll
    for (int i = 0; i < 16; i++) p[tid + i * 256] = v[i] * inv;
}

// ---------------------------------------------------------------------------
// Host launcher (graph-capturable: kernel launches only)
// ---------------------------------------------------------------------------
extern "C" void kernel_launch(void* const* d_in, const int* in_sizes, int n_in,
                              void* d_out, int out_size)
{
    (void)in_sizes; (void)n_in; (void)out_size;
    const float* x     = (const float*)d_in[0];
    const float* query = (const float*)d_in[1];
    const float* Wq = (const float*)d_in[2];  const float* bq = (const float*)d_in[3];
    const float* Wk = (const float*)d_in[4];  const float* bk = (const float*)d_in[5];
    const float* Wv = (const float*)d_in[6];  const float* bv = (const float*)d_in[7];
    const float* W1 = (const float*)d_in[8];  const float* b1 = (const float*)d_in[9];
    const float* W2 = (const float*)d_in[10]; const float* b2 = (const float*)d_in[11];
    const float* W3 = (const float*)d_in[12]; const float* b3 = (const float*)d_in[13];

    float* outp = (float*)d_out;
    float* hout = outp;                                    // [4,4096,256]
    float* attn = outp + (size_t)4 * 4096 * 256;           // [4,4096,4096]

    float *q, *k, *v, *t0, *vt;
    cudaGetSymbolAddress((void**)&q,  g_q);
    cudaGetSymbolAddress((void**)&k,  g_k);
    cudaGetSymbolAddress((void**)&v,  g_v);
    cudaGetSymbolAddress((void**)&t0, g_t0);
    cudaGetSymbolAddress((void**)&vt, g_t1);               // V^T, then MLP temp

    const int Mtot = 4 * 4096;
    const int D = 256;
    const int S = 4096;
    const dim3 blk(256);
    const dim3 gLin(D / 128, Mtot / 128, 1);    // (2, 128, 1)

    // q/k/v projections (HMMA): y = x @ W^T + b
    gemm_hmma_nt<<<gLin, blk>>>(query, Wq, bq, q, Mtot, D, D, 0, 0, 0, 1.0f, 0);
    gemm_hmma_nt<<<gLin, blk>>>(x,     Wk, bk, k, Mtot, D, D, 0, 0, 0, 1.0f, 0);
    gemm_hmma_nt<<<gLin, blk>>>(x,     Wv, bv, v, Mtot, D, D, 0, 0, 0, 1.0f, 0);

    // V^T per batch (for tensor-core AV)
    transpose256<<<dim3(S / 32, D / 32, 4), 256>>>(v, vt);

    // scores = (q @ k^T) / sqrt(D) -> attn output slot  (HMMA)
    gemm_hmma_nt<<<dim3(S / 128, S / 128, 4), blk>>>(
        q, k, nullptr, attn, S, S, D,
        (long long)S * D, (long long)S * D, (long long)S * S, 0.0625f, 0);

    // softmax rows, in place (fp32)
    softmax_rows<<<Mtot, blk>>>(attn);

    // out = attn @ V = attn @ (V^T)^T  (HMMA)
    gemm_hmma_nt<<<dim3(D / 128, S / 128, 4), blk>>>(
        attn, vt, nullptr, t0, S, D, S,
        (long long)S * S, (long long)D * S, (long long)S * D, 1.0f, 0);

    // MLP (HMMA): three relu(linear) layers, last writes h output
    gemm_hmma_nt<<<gLin, blk>>>(t0, W1, b1, vt,   Mtot, D, D, 0, 0, 0, 1.0f, 1);
    gemm_hmma_nt<<<gLin, blk>>>(vt, W2, b2, t0,   Mtot, D, D, 0, 0, 0, 1.0f, 1);
    gemm_hmma_nt<<<gLin, blk>>>(t0, W3, b3, hout, Mtot, D, D, 0, 0, 0, 1.0f, 1);
}

// round 11
// speedup vs baseline: 3.2958x; 1.7356x over previous
#include <cuda_runtime.h>
#include <cuda_fp16.h>
#include <cstdint>
#include <cstddef>

// ---------------------------------------------------------------------------
// Problem constants: B=4, NQ=NK=4096, D=256
// d_out = [ h: 4*4096*256 | attn: 4*4096*4096 ]
// ---------------------------------------------------------------------------

// Scratch (device globals: allocation inside kernel_launch is forbidden)
__device__ __half g_xh [4 * 4096 * 256];
__device__ __half g_qh [4 * 4096 * 256];
__device__ __half g_q  [4 * 4096 * 256];
__device__ __half g_k  [4 * 4096 * 256];
__device__ __half g_v  [4 * 4096 * 256];
__device__ __half g_vt [4 * 4096 * 256];
__device__ __half g_t0 [4 * 4096 * 256];
__device__ __half g_t1 [4 * 4096 * 256];
__device__ __half g_w  [6][256 * 256];
__device__ __half g_ah [(size_t)4 * 4096 * 4096];   // fp16 attn copy for AV

static __device__ __forceinline__ uint32_t smem_u32(const void* p) {
    uint32_t a;
    asm("{ .reg .u64 t; cvta.to.shared.u64 t, %1; cvt.u32.u64 %0, t; }"
        : "=r"(a) : "l"(p));
    return a;
}
static __device__ __forceinline__ uint32_t f2h2(float x, float y) {
    uint32_t r;
    asm("cvt.rn.f16x2.f32 %0, %1, %2;" : "=r"(r) : "f"(y), "f"(x));
    return r;
}
static __device__ __forceinline__ void cp16(uint32_t s, const void* g) {
    asm volatile("cp.async.cg.shared.global [%0], [%1], 16;" :: "r"(s), "l"(g));
}
#define CP_COMMIT() asm volatile("cp.async.commit_group;" ::: "memory")
#define CP_WAIT(n)  asm volatile("cp.async.wait_group %0;" :: "n"(n) : "memory")

// epilogue paired store: fp32 or fp16 destination
static __device__ __forceinline__ void store2(float* C, size_t idx, float x, float y) {
    *(float2*)(C + idx) = make_float2(x, y);
}
static __device__ __forceinline__ void store2(__half* C, size_t idx, float x, float y) {
    *(__half2*)(C + idx) = __floats2half2_rn(x, y);
}

// ===========================================================================
// HMMA fp16 NT GEMM: C[M,N] = alpha * A[M,K] * B[N,K]^T (+bias, +relu)
//   fp16 operands in gmem (cp.async 16B direct to smem), fp32 accumulate,
//   TOut = float or __half.
//   CTA tile 128x128, BK=32. 8 warps = 2(m) x 4(n); warp tile 64x32.
//   Smem rows = 32 fp16 + 8 pad = 80B (5 x 16B): stride 5 mod 8 in 16B banks
//   -> conflict-free ldmatrix by construction.
//   Requires M%128==0, N%128==0, K%32==0.
// ===========================================================================
#define H_ROW   40                   // fp16 per smem row (32 data + 8 pad)
#define H_MAT   (128 * H_ROW)        // 5120 halfs = 10240 B per matrix
#define H_BUF   (2 * H_MAT)          // A + B per buffer (halfs)

template <typename TOut>
__global__ void __launch_bounds__(256, 2) gemm_h_nt(
    const __half* __restrict__ A, const __half* __restrict__ B,
    const float* __restrict__ bias, TOut* __restrict__ C,
    int M, int N, int K,
    long long sA, long long sB, long long sC,
    float alpha, int relu)
{
    __shared__ __align__(16) __half sm[2 * H_BUF];   // 40960 B

    A += (size_t)blockIdx.z * (size_t)sA;
    B += (size_t)blockIdx.z * (size_t)sB;
    C += (size_t)blockIdx.z * (size_t)sC;
    const int m0 = blockIdx.y * 128;
    const int n0 = blockIdx.x * 128;
    const int tid = threadIdx.x;
    const int w = tid >> 5;
    const int l = tid & 31;

    // ---- async loader mapping: row w*16+(l&15), 16B-chunks {2*(l>>4), +1}
    const int lrow = w * 16 + (l & 15);
    const int lc   = (l >> 4) * 2;
    const uint32_t smem_base = smem_u32(sm);
    const uint32_t sa = smem_base + (uint32_t)(lrow * 80 + lc * 16);
    const uint32_t sb = sa + (uint32_t)(H_MAT * 2);
    const __half* ag = A + (size_t)(m0 + lrow) * (size_t)K + lc * 8;
    const __half* bg = B + (size_t)(n0 + lrow) * (size_t)K + lc * 8;

    auto copy_chunk = [&](int c, int buf) {
        const uint32_t off = (uint32_t)buf * (H_BUF * 2);
        const __half* a = ag + c * 32;
        const __half* b = bg + c * 32;
        cp16(sa + off, a);      cp16(sa + off + 16, a + 8);
        cp16(sb + off, b);      cp16(sb + off + 16, b + 8);
    };

    // ---- compute mapping
    const int wm = (w & 1) * 64;
    const int wn = (w >> 1) * 32;
    const uint32_t aoff = (uint32_t)((wm + (l & 15)) * 80 + (l >> 4) * 16);
    const uint32_t boff = (uint32_t)((wn + (l & 7)) * 80 + ((l >> 3) & 1) * 16);

    float acc[4][4][4];
#pragma unroll
    for (int i = 0; i < 4; i++)
#pragma unroll
        for (int j = 0; j < 4; j++)
#pragma unroll
            for (int q = 0; q < 4; q++) acc[i][j][q] = 0.0f;

    const int nch = K / 32;

    copy_chunk(0, 0);
    CP_COMMIT();

    for (int c = 0; c < nch; c++) {
        const int buf = c & 1;
        if (c + 1 < nch) {
            copy_chunk(c + 1, buf ^ 1);
            CP_COMMIT();
            CP_WAIT(1);                 // group c complete; c+1 may remain
        } else {
            CP_WAIT(0);
        }
        __syncthreads();

        const uint32_t aB = smem_base + (uint32_t)buf * (H_BUF * 2);
        const uint32_t bB = aB + (uint32_t)(H_MAT * 2);
#pragma unroll
        for (int s = 0; s < 2; s++) {
            uint32_t af[4][4];
#pragma unroll
            for (int ma = 0; ma < 4; ma++) {
                const uint32_t addr = aB + aoff + (uint32_t)(ma * 16 * 80 + s * 32);
                asm volatile(
                    "ldmatrix.sync.aligned.m8n8.x4.shared.b16 {%0,%1,%2,%3}, [%4];"
                    : "=r"(af[ma][0]), "=r"(af[ma][1]),
                      "=r"(af[ma][2]), "=r"(af[ma][3])
                    : "r"(addr));
            }
            uint32_t bf[4][2];
#pragma unroll
            for (int na = 0; na < 4; na++) {
                const uint32_t addr = bB + boff + (uint32_t)(na * 8 * 80 + s * 32);
                asm volatile(
                    "ldmatrix.sync.aligned.m8n8.x2.shared.b16 {%0,%1}, [%2];"
                    : "=r"(bf[na][0]), "=r"(bf[na][1])
                    : "r"(addr));
            }
#pragma unroll
            for (int ma = 0; ma < 4; ma++)
#pragma unroll
                for (int na = 0; na < 4; na++) {
                    asm volatile(
                        "mma.sync.aligned.m16n8k16.row.col.f32.f16.f16.f32 "
                        "{%0,%1,%2,%3}, {%4,%5,%6,%7}, {%8,%9}, {%0,%1,%2,%3};"
                        : "+f"(acc[ma][na][0]), "+f"(acc[ma][na][1]),
                          "+f"(acc[ma][na][2]), "+f"(acc[ma][na][3])
                        : "r"(af[ma][0]), "r"(af[ma][1]),
                          "r"(af[ma][2]), "r"(af[ma][3]),
                          "r"(bf[na][0]), "r"(bf[na][1]));
                }
        }
        __syncthreads();
    }

    // ---- epilogue
    const int erow = m0 + wm + (l >> 2);
    const int ecol = n0 + wn + (l & 3) * 2;
#pragma unroll
    for (int ma = 0; ma < 4; ma++) {
        const int r = erow + ma * 16;
#pragma unroll
        for (int na = 0; na < 4; na++) {
            const int cc = ecol + na * 8;
            float2 bb = make_float2(0.f, 0.f);
            if (bias) bb = *(const float2*)(bias + cc);
            float lx = alpha * acc[ma][na][0] + bb.x;
            float ly = alpha * acc[ma][na][1] + bb.y;
            float hx = alpha * acc[ma][na][2] + bb.x;
            float hy = alpha * acc[ma][na][3] + bb.y;
            if (relu) {
                lx = fmaxf(lx, 0.f); ly = fmaxf(ly, 0.f);
                hx = fmaxf(hx, 0.f); hy = fmaxf(hy, 0.f);
            }
            store2(C, (size_t)r * (size_t)N + cc, lx, ly);
            store2(C, (size_t)(r + 8) * (size_t)N + cc, hx, hy);
        }
    }
}

// ===========================================================================
// fp32 -> fp16 convert (n % 8 == 0)
// ===========================================================================
__global__ void __launch_bounds__(256) f2h_kernel(
    const float* __restrict__ s, __half* __restrict__ d, int n)
{
    const int i = (blockIdx.x * 256 + threadIdx.x) * 8;
    if (i >= n) return;
    float4 u = *(const float4*)(s + i);
    float4 v = *(const float4*)(s + i + 4);
    uint4 o;
    o.x = f2h2(u.x, u.y); o.y = f2h2(u.z, u.w);
    o.z = f2h2(v.x, v.y); o.w = f2h2(v.z, v.w);
    *(uint4*)(d + i) = o;
}

// ===========================================================================
// V transpose (fp16): vt[b][d][t] = v[b][t][d]
// ===========================================================================
__global__ void __launch_bounds__(256) transpose256h(
    const __half* __restrict__ src, __half* __restrict__ dst)
{
    __shared__ __half t[32][34];
    const int b = blockIdx.z;
    const int k0 = blockIdx.x * 32, n0 = blockIdx.y * 32;
    const __half* s = src + (size_t)b * 4096 * 256;
    __half* d = dst + (size_t)b * 4096 * 256;
    const int tx = threadIdx.x & 31, ty = (threadIdx.x >> 5) * 4;
#pragma unroll
    for (int i = 0; i < 4; i++)
        t[ty + i][tx] = s[(size_t)(k0 + ty + i) * 256 + n0 + tx];
    __syncthreads();
#pragma unroll
    for (int i = 0; i < 4; i++)
        d[(size_t)(n0 + ty + i) * 4096 + k0 + tx] = t[tx][ty + i];
}

// ---------------------------------------------------------------------------
// Row softmax in place over attn[16384][4096] (fp32) + fp16 copy for AV.
// ---------------------------------------------------------------------------
static __device__ __forceinline__ float warpMax(float v) {
#pragma unroll
    for (int o = 16; o > 0; o >>= 1) v = fmaxf(v, __shfl_xor_sync(0xffffffffu, v, o));
    return v;
}
static __device__ __forceinline__ float warpSum(float v) {
#pragma unroll
    for (int o = 16; o > 0; o >>= 1) v += __shfl_xor_sync(0xffffffffu, v, o);
    return v;
}

__global__ void __launch_bounds__(256) softmax_rows(
    float* __restrict__ attn, __half* __restrict__ ah)
{
    __shared__ float red[8];
    __shared__ float bcast;
    const size_t row = blockIdx.x;
    float* p = attn + row * 4096;
    __half* ph = ah + row * 4096;
    const int tid = threadIdx.x;

    float v[16];
#pragma unroll
    for (int i = 0; i < 16; i++) v[i] = p[tid + i * 256];

    float m = v[0];
#pragma unroll
    for (int i = 1; i < 16; i++) m = fmaxf(m, v[i]);
    m = warpMax(m);
    if ((tid & 31) == 0) red[tid >> 5] = m;
    __syncthreads();
    if (tid < 32) {
        float t = (tid < 8) ? red[tid] : -3.4e38f;
        t = warpMax(t);
        if (tid == 0) bcast = t;
    }
    __syncthreads();
    m = bcast;

    float s = 0.0f;
#pragma unroll
    for (int i = 0; i < 16; i++) { v[i] = __expf(v[i] - m); s += v[i]; }
    s = warpSum(s);
    __syncthreads();
    if ((tid & 31) == 0) red[tid >> 5] = s;
    __syncthreads();
    if (tid < 32) {
        float t = (tid < 8) ? red[tid] : 0.0f;
        t = warpSum(t);
        if (tid == 0) bcast = t;
    }
    __syncthreads();
    const float inv = 1.0f / bcast;
#pragma unroll
    for (int i = 0; i < 16; i++) {
        const float r = v[i] * inv;
        p[tid + i * 256]  = r;
        ph[tid + i * 256] = __float2half_rn(r);
    }
}

// ---------------------------------------------------------------------------
// Host launcher (graph-capturable: kernel launches only)
// ---------------------------------------------------------------------------
extern "C" void kernel_launch(void* const* d_in, const int* in_sizes, int n_in,
                              void* d_out, int out_size)
{
    (void)in_sizes; (void)n_in; (void)out_size;
    const float* x     = (const float*)d_in[0];
    const float* query = (const float*)d_in[1];
    const float* Wq = (const float*)d_in[2];  const float* bq = (const float*)d_in[3];
    const float* Wk = (const float*)d_in[4];  const float* bk = (const float*)d_in[5];
    const float* Wv = (const float*)d_in[6];  const float* bv = (const float*)d_in[7];
    const float* W1 = (const float*)d_in[8];  const float* b1 = (const float*)d_in[9];
    const float* W2 = (const float*)d_in[10]; const float* b2 = (const float*)d_in[11];
    const float* W3 = (const float*)d_in[12]; const float* b3 = (const float*)d_in[13];

    float* outp = (float*)d_out;
    float* hout = outp;                                    // [4,4096,256]
    float* attn = outp + (size_t)4 * 4096 * 256;           // [4,4096,4096]

    __half *xh, *qh, *q, *k, *v, *vt, *t0, *t1, *wh, *ah;
    cudaGetSymbolAddress((void**)&xh, g_xh);
    cudaGetSymbolAddress((void**)&qh, g_qh);
    cudaGetSymbolAddress((void**)&q,  g_q);
    cudaGetSymbolAddress((void**)&k,  g_k);
    cudaGetSymbolAddress((void**)&v,  g_v);
    cudaGetSymbolAddress((void**)&vt, g_vt);
    cudaGetSymbolAddress((void**)&t0, g_t0);
    cudaGetSymbolAddress((void**)&t1, g_t1);
    cudaGetSymbolAddress((void**)&wh, g_w);
    cudaGetSymbolAddress((void**)&ah, g_ah);

    const int Mtot = 4 * 4096;
    const int D = 256;
    const int S = 4096;
    const int NW = D * D;              // 65536 weight elems
    const dim3 blk(256);
    const dim3 gLin(D / 128, Mtot / 128, 1);    // (2, 128, 1)

    // ---- fp32 -> fp16 conversions (inputs + weights)
    const int nBig = Mtot * D;         // 4,194,304
    f2h_kernel<<<nBig / 2048, 256>>>(x,     xh, nBig);
    f2h_kernel<<<nBig / 2048, 256>>>(query, qh, nBig);
    f2h_kernel<<<NW / 2048, 256>>>(Wq, wh + 0 * NW, NW);
    f2h_kernel<<<NW / 2048, 256>>>(Wk, wh + 1 * NW, NW);
    f2h_kernel<<<NW / 2048, 256>>>(Wv, wh + 2 * NW, NW);
    f2h_kernel<<<NW / 2048, 256>>>(W1, wh + 3 * NW, NW);
    f2h_kernel<<<NW / 2048, 256>>>(W2, wh + 4 * NW, NW);
    f2h_kernel<<<NW / 2048, 256>>>(W3, wh + 5 * NW, NW);

    // ---- q/k/v projections: y = x @ W^T + b   (fp16 out)
    gemm_h_nt<__half><<<gLin, blk>>>(qh, wh + 0 * NW, bq, q, Mtot, D, D, 0, 0, 0, 1.0f, 0);
    gemm_h_nt<__half><<<gLin, blk>>>(xh, wh + 1 * NW, bk, k, Mtot, D, D, 0, 0, 0, 1.0f, 0);
    gemm_h_nt<__half><<<gLin, blk>>>(xh, wh + 2 * NW, bv, v, Mtot, D, D, 0, 0, 0, 1.0f, 0);

    // ---- V^T per batch (fp16)
    transpose256h<<<dim3(S / 32, D / 32, 4), 256>>>(v, vt);

    // ---- scores = (q @ k^T) / sqrt(D) -> attn output slot (fp32 out)
    gemm_h_nt<float><<<dim3(S / 128, S / 128, 4), blk>>>(
        q, k, nullptr, attn, S, S, D,
        (long long)S * D, (long long)S * D, (long long)S * S, 0.0625f, 0);

    // ---- softmax rows in place (fp32) + fp16 copy
    softmax_rows<<<Mtot, blk>>>(attn, ah);

    // ---- out = attn @ V = attn_h @ (V^T)^T  (fp16 out)
    gemm_h_nt<__half><<<dim3(D / 128, S / 128, 4), blk>>>(
        ah, vt, nullptr, t0, S, D, S,
        (long long)S * S, (long long)D * S, (long long)S * D, 1.0f, 0);

    // ---- MLP: three relu(linear) layers; last writes fp32 h output
    gemm_h_nt<__half><<<gLin, blk>>>(t0, wh + 3 * NW, b1, t1, Mtot, D, D, 0, 0, 0, 1.0f, 1);
    gemm_h_nt<__half><<<gLin, blk>>>(t1, wh + 4 * NW, b2, t0, Mtot, D, D, 0, 0, 0, 1.0f, 1);
    gemm_h_nt<float ><<<gLin, blk>>>(t0, wh + 5 * NW, b3, hout, Mtot, D, D, 0, 0, 0, 1.0f, 1);
}

// round 12
// speedup vs baseline: 3.7144x; 1.1270x over previous
#include <cuda_runtime.h>
#include <cuda_fp16.h>
#include <cstdint>
#include <cstddef>

// ---------------------------------------------------------------------------
// Problem constants: B=4, NQ=NK=4096, D=256
// d_out = [ h: 4*4096*256 | attn: 4*4096*4096 ]
// ---------------------------------------------------------------------------

// Scratch (device globals: allocation inside kernel_launch is forbidden)
__device__ __half g_xh [4 * 4096 * 256];
__device__ __half g_qh [4 * 4096 * 256];
__device__ __half g_q  [4 * 4096 * 256];
__device__ __half g_k  [4 * 4096 * 256];
__device__ __half g_v  [4 * 4096 * 256];
__device__ __half g_vt [4 * 4096 * 256];
__device__ __half g_t0 [4 * 4096 * 256];
__device__ __half g_t1 [4 * 4096 * 256];
__device__ __half g_w  [6][256 * 256];
__device__ __half g_ah [(size_t)4 * 4096 * 4096];   // fp16 attn copy for AV

static __device__ __forceinline__ uint32_t smem_u32(const void* p) {
    uint32_t a;
    asm("{ .reg .u64 t; cvta.to.shared.u64 t, %1; cvt.u32.u64 %0, t; }"
        : "=r"(a) : "l"(p));
    return a;
}
static __device__ __forceinline__ uint32_t f2h2(float x, float y) {
    uint32_t r;
    asm("cvt.rn.f16x2.f32 %0, %1, %2;" : "=r"(r) : "f"(y), "f"(x));
    return r;
}
static __device__ __forceinline__ void cp16(uint32_t s, const void* g) {
    asm volatile("cp.async.cg.shared.global [%0], [%1], 16;" :: "r"(s), "l"(g));
}
#define CP_COMMIT() asm volatile("cp.async.commit_group;" ::: "memory")
#define CP_WAIT(n)  asm volatile("cp.async.wait_group %0;" :: "n"(n) : "memory")

// epilogue paired store: fp32 or fp16 destination
static __device__ __forceinline__ void store2(float* C, size_t idx, float x, float y) {
    *(float2*)(C + idx) = make_float2(x, y);
}
static __device__ __forceinline__ void store2(__half* C, size_t idx, float x, float y) {
    *(__half2*)(C + idx) = __floats2half2_rn(x, y);
}

// ===========================================================================
// HMMA fp16 NT GEMM: C[M,N] = alpha * A[M,K] * B[N,K]^T (+bias, +relu)
//   fp16 operands in gmem (cp.async 16B direct to smem), fp32 accumulate,
//   TOut = float or __half.
//   CTA tile 128x128, BK=32; 3-stage circular cp.async pipeline in dynamic
//   smem (one __syncthreads per chunk, prefetch distance 2).
//   8 warps = 2(m) x 4(n); warp tile 64x32.
//   Smem rows = 32 fp16 + 8 pad = 80B (5 x 16B): stride 5 mod 8 in 16B banks
//   -> conflict-free ldmatrix by construction.
//   Requires M%128==0, N%128==0, K%32==0.
// ===========================================================================
#define H_ROW   40                   // fp16 per smem row (32 data + 8 pad)
#define H_MAT   (128 * H_ROW)        // 5120 halfs = 10240 B per matrix
#define STAGE_B (2 * H_MAT * 2)      // A+B bytes per stage = 20480
#define NSTAGE  3
#define GEMM_SMEM (NSTAGE * STAGE_B) // 61440 B dynamic

template <typename TOut>
__global__ void __launch_bounds__(256, 2) gemm_h_nt(
    const __half* __restrict__ A, const __half* __restrict__ B,
    const float* __restrict__ bias, TOut* __restrict__ C,
    int M, int N, int K,
    long long sA, long long sB, long long sC,
    float alpha, int relu)
{
    extern __shared__ __align__(16) __half smd[];

    A += (size_t)blockIdx.z * (size_t)sA;
    B += (size_t)blockIdx.z * (size_t)sB;
    C += (size_t)blockIdx.z * (size_t)sC;
    const int m0 = blockIdx.y * 128;
    const int n0 = blockIdx.x * 128;
    const int tid = threadIdx.x;
    const int w = tid >> 5;
    const int l = tid & 31;

    // ---- async loader mapping: row w*16+(l&15), 16B-chunks {2*(l>>4), +1}
    const int lrow = w * 16 + (l & 15);
    const int lc   = (l >> 4) * 2;
    const uint32_t smem_base = smem_u32(smd);
    const uint32_t sa = smem_base + (uint32_t)(lrow * 80 + lc * 16);
    const uint32_t sb = sa + (uint32_t)(H_MAT * 2);
    const __half* ag = A + (size_t)(m0 + lrow) * (size_t)K + lc * 8;
    const __half* bg = B + (size_t)(n0 + lrow) * (size_t)K + lc * 8;

    auto copy_chunk = [&](int c, int st) {
        const uint32_t off = (uint32_t)st * STAGE_B;
        const __half* a = ag + c * 32;
        const __half* b = bg + c * 32;
        cp16(sa + off, a);      cp16(sa + off + 16, a + 8);
        cp16(sb + off, b);      cp16(sb + off + 16, b + 8);
    };

    // ---- compute mapping
    const int wm = (w & 1) * 64;
    const int wn = (w >> 1) * 32;
    const uint32_t aoff = (uint32_t)((wm + (l & 15)) * 80 + (l >> 4) * 16);
    const uint32_t boff = (uint32_t)((wn + (l & 7)) * 80 + ((l >> 3) & 1) * 16);

    float acc[4][4][4];
#pragma unroll
    for (int i = 0; i < 4; i++)
#pragma unroll
        for (int j = 0; j < 4; j++)
#pragma unroll
            for (int q = 0; q < 4; q++) acc[i][j][q] = 0.0f;

    const int nch = K / 32;          // >= 8 for all shapes here

    // prologue: stages 0,1 <- chunks 0,1
    copy_chunk(0, 0); CP_COMMIT();
    copy_chunk(1, 1); CP_COMMIT();

    int st_cmp = 0;                  // stage holding chunk c
    int st_cpy = 2;                  // stage to receive chunk c+2
    for (int c = 0; c < nch; c++) {
        CP_WAIT(1);                  // chunk c resident
        __syncthreads();             // visible to all warps; stage st_cpy free

        if (c + 2 < nch) copy_chunk(c + 2, st_cpy);
        CP_COMMIT();                 // commit every iter (group numbering)

        const uint32_t aB = smem_base + (uint32_t)st_cmp * STAGE_B;
        const uint32_t bB = aB + (uint32_t)(H_MAT * 2);
#pragma unroll
        for (int s = 0; s < 2; s++) {
            uint32_t af[4][4];
#pragma unroll
            for (int ma = 0; ma < 4; ma++) {
                const uint32_t addr = aB + aoff + (uint32_t)(ma * 16 * 80 + s * 32);
                asm volatile(
                    "ldmatrix.sync.aligned.m8n8.x4.shared.b16 {%0,%1,%2,%3}, [%4];"
                    : "=r"(af[ma][0]), "=r"(af[ma][1]),
                      "=r"(af[ma][2]), "=r"(af[ma][3])
                    : "r"(addr));
            }
            uint32_t bf[4][2];
#pragma unroll
            for (int na = 0; na < 4; na++) {
                const uint32_t addr = bB + boff + (uint32_t)(na * 8 * 80 + s * 32);
                asm volatile(
                    "ldmatrix.sync.aligned.m8n8.x2.shared.b16 {%0,%1}, [%2];"
                    : "=r"(bf[na][0]), "=r"(bf[na][1])
                    : "r"(addr));
            }
#pragma unroll
            for (int ma = 0; ma < 4; ma++)
#pragma unroll
                for (int na = 0; na < 4; na++) {
                    asm volatile(
                        "mma.sync.aligned.m16n8k16.row.col.f32.f16.f16.f32 "
                        "{%0,%1,%2,%3}, {%4,%5,%6,%7}, {%8,%9}, {%0,%1,%2,%3};"
                        : "+f"(acc[ma][na][0]), "+f"(acc[ma][na][1]),
                          "+f"(acc[ma][na][2]), "+f"(acc[ma][na][3])
                        : "r"(af[ma][0]), "r"(af[ma][1]),
                          "r"(af[ma][2]), "r"(af[ma][3]),
                          "r"(bf[na][0]), "r"(bf[na][1]));
                }
        }
        st_cmp = (st_cmp == NSTAGE - 1) ? 0 : st_cmp + 1;
        st_cpy = (st_cpy == NSTAGE - 1) ? 0 : st_cpy + 1;
    }

    // ---- epilogue
    const int erow = m0 + wm + (l >> 2);
    const int ecol = n0 + wn + (l & 3) * 2;
#pragma unroll
    for (int ma = 0; ma < 4; ma++) {
        const int r = erow + ma * 16;
#pragma unroll
        for (int na = 0; na < 4; na++) {
            const int cc = ecol + na * 8;
            float2 bb = make_float2(0.f, 0.f);
            if (bias) bb = *(const float2*)(bias + cc);
            float lx = alpha * acc[ma][na][0] + bb.x;
            float ly = alpha * acc[ma][na][1] + bb.y;
            float hx = alpha * acc[ma][na][2] + bb.x;
            float hy = alpha * acc[ma][na][3] + bb.y;
            if (relu) {
                lx = fmaxf(lx, 0.f); ly = fmaxf(ly, 0.f);
                hx = fmaxf(hx, 0.f); hy = fmaxf(hy, 0.f);
            }
            store2(C, (size_t)r * (size_t)N + cc, lx, ly);
            store2(C, (size_t)(r + 8) * (size_t)N + cc, hx, hy);
        }
    }
}

// ===========================================================================
// fp32 -> fp16 convert (n % 8 == 0)
// ===========================================================================
__global__ void __launch_bounds__(256) f2h_kernel(
    const float* __restrict__ s, __half* __restrict__ d, int n)
{
    const int i = (blockIdx.x * 256 + threadIdx.x) * 8;
    if (i >= n) return;
    float4 u = *(const float4*)(s + i);
    float4 v = *(const float4*)(s + i + 4);
    uint4 o;
    o.x = f2h2(u.x, u.y); o.y = f2h2(u.z, u.w);
    o.z = f2h2(v.x, v.y); o.w = f2h2(v.z, v.w);
    *(uint4*)(d + i) = o;
}

// ===========================================================================
// V transpose (fp16): vt[b][d][t] = v[b][t][d]
// ===========================================================================
__global__ void __launch_bounds__(256) transpose256h(
    const __half* __restrict__ src, __half* __restrict__ dst)
{
    __shared__ __half t[32][34];
    const int b = blockIdx.z;
    const int k0 = blockIdx.x * 32, n0 = blockIdx.y * 32;
    const __half* s = src + (size_t)b * 4096 * 256;
    __half* d = dst + (size_t)b * 4096 * 256;
    const int tx = threadIdx.x & 31, ty = (threadIdx.x >> 5) * 4;
#pragma unroll
    for (int i = 0; i < 4; i++)
        t[ty + i][tx] = s[(size_t)(k0 + ty + i) * 256 + n0 + tx];
    __syncthreads();
#pragma unroll
    for (int i = 0; i < 4; i++)
        d[(size_t)(n0 + ty + i) * 4096 + k0 + tx] = t[tx][ty + i];
}

// ---------------------------------------------------------------------------
// Row softmax in place over attn[16384][4096] (fp32) + fp16 copy for AV.
// ---------------------------------------------------------------------------
static __device__ __forceinline__ float warpMax(float v) {
#pragma unroll
    for (int o = 16; o > 0; o >>= 1) v = fmaxf(v, __shfl_xor_sync(0xffffffffu, v, o));
    return v;
}
static __device__ __forceinline__ float warpSum(float v) {
#pragma unroll
    for (int o = 16; o > 0; o >>= 1) v += __shfl_xor_sync(0xffffffffu, v, o);
    return v;
}

__global__ void __launch_bounds__(256) softmax_rows(
    float* __restrict__ attn, __half* __restrict__ ah)
{
    __shared__ float red[8];
    __shared__ float bcast;
    const size_t row = blockIdx.x;
    float* p = attn + row * 4096;
    __half* ph = ah + row * 4096;
    const int tid = threadIdx.x;

    float v[16];
#pragma unroll
    for (int i = 0; i < 16; i++) v[i] = p[tid + i * 256];

    float m = v[0];
#pragma unroll
    for (int i = 1; i < 16; i++) m = fmaxf(m, v[i]);
    m = warpMax(m);
    if ((tid & 31) == 0) red[tid >> 5] = m;
    __syncthreads();
    if (tid < 32) {
        float t = (tid < 8) ? red[tid] : -3.4e38f;
        t = warpMax(t);
        if (tid == 0) bcast = t;
    }
    __syncthreads();
    m = bcast;

    float s = 0.0f;
#pragma unroll
    for (int i = 0; i < 16; i++) { v[i] = __expf(v[i] - m); s += v[i]; }
    s = warpSum(s);
    __syncthreads();
    if ((tid & 31) == 0) red[tid >> 5] = s;
    __syncthreads();
    if (tid < 32) {
        float t = (tid < 8) ? red[tid] : 0.0f;
        t = warpSum(t);
        if (tid == 0) bcast = t;
    }
    __syncthreads();
    const float inv = 1.0f / bcast;
#pragma unroll
    for (int i = 0; i < 16; i++) {
        const float r = v[i] * inv;
        p[tid + i * 256]  = r;
        ph[tid + i * 256] = __float2half_rn(r);
    }
}

// ---------------------------------------------------------------------------
// Host launcher (graph-capturable: kernel launches only)
// ---------------------------------------------------------------------------
extern "C" void kernel_launch(void* const* d_in, const int* in_sizes, int n_in,
                              void* d_out, int out_size)
{
    (void)in_sizes; (void)n_in; (void)out_size;
    const float* x     = (const float*)d_in[0];
    const float* query = (const float*)d_in[1];
    const float* Wq = (const float*)d_in[2];  const float* bq = (const float*)d_in[3];
    const float* Wk = (const float*)d_in[4];  const float* bk = (const float*)d_in[5];
    const float* Wv = (const float*)d_in[6];  const float* bv = (const float*)d_in[7];
    const float* W1 = (const float*)d_in[8];  const float* b1 = (const float*)d_in[9];
    const float* W2 = (const float*)d_in[10]; const float* b2 = (const float*)d_in[11];
    const float* W3 = (const float*)d_in[12]; const float* b3 = (const float*)d_in[13];

    float* outp = (float*)d_out;
    float* hout = outp;                                    // [4,4096,256]
    float* attn = outp + (size_t)4 * 4096 * 256;           // [4,4096,4096]

    __half *xh, *qh, *q, *k, *v, *vt, *t0, *t1, *wh, *ah;
    cudaGetSymbolAddress((void**)&xh, g_xh);
    cudaGetSymbolAddress((void**)&qh, g_qh);
    cudaGetSymbolAddress((void**)&q,  g_q);
    cudaGetSymbolAddress((void**)&k,  g_k);
    cudaGetSymbolAddress((void**)&v,  g_v);
    cudaGetSymbolAddress((void**)&vt, g_vt);
    cudaGetSymbolAddress((void**)&t0, g_t0);
    cudaGetSymbolAddress((void**)&t1, g_t1);
    cudaGetSymbolAddress((void**)&wh, g_w);
    cudaGetSymbolAddress((void**)&ah, g_ah);

    // allow 60KB dynamic smem (idempotent; no allocation involved)
    cudaFuncSetAttribute(gemm_h_nt<__half>,
                         cudaFuncAttributeMaxDynamicSharedMemorySize, GEMM_SMEM);
    cudaFuncSetAttribute(gemm_h_nt<float>,
                         cudaFuncAttributeMaxDynamicSharedMemorySize, GEMM_SMEM);

    const int Mtot = 4 * 4096;
    const int D = 256;
    const int S = 4096;
    const int NW = D * D;              // 65536 weight elems
    const dim3 blk(256);
    const dim3 gLin(D / 128, Mtot / 128, 1);    // (2, 128, 1)

    // ---- fp32 -> fp16 conversions (inputs + weights)
    const int nBig = Mtot * D;         // 4,194,304
    f2h_kernel<<<nBig / 2048, 256>>>(x,     xh, nBig);
    f2h_kernel<<<nBig / 2048, 256>>>(query, qh, nBig);
    f2h_kernel<<<NW / 2048, 256>>>(Wq, wh + 0 * NW, NW);
    f2h_kernel<<<NW / 2048, 256>>>(Wk, wh + 1 * NW, NW);
    f2h_kernel<<<NW / 2048, 256>>>(Wv, wh + 2 * NW, NW);
    f2h_kernel<<<NW / 2048, 256>>>(W1, wh + 3 * NW, NW);
    f2h_kernel<<<NW / 2048, 256>>>(W2, wh + 4 * NW, NW);
    f2h_kernel<<<NW / 2048, 256>>>(W3, wh + 5 * NW, NW);

    // ---- q/k/v projections: y = x @ W^T + b   (fp16 out)
    gemm_h_nt<__half><<<gLin, blk, GEMM_SMEM>>>(qh, wh + 0 * NW, bq, q, Mtot, D, D, 0, 0, 0, 1.0f, 0);
    gemm_h_nt<__half><<<gLin, blk, GEMM_SMEM>>>(xh, wh + 1 * NW, bk, k, Mtot, D, D, 0, 0, 0, 1.0f, 0);
    gemm_h_nt<__half><<<gLin, blk, GEMM_SMEM>>>(xh, wh + 2 * NW, bv, v, Mtot, D, D, 0, 0, 0, 1.0f, 0);

    // ---- V^T per batch (fp16)
    transpose256h<<<dim3(S / 32, D / 32, 4), 256>>>(v, vt);

    // ---- scores = (q @ k^T) / sqrt(D) -> attn output slot (fp32 out)
    gemm_h_nt<float><<<dim3(S / 128, S / 128, 4), blk, GEMM_SMEM>>>(
        q, k, nullptr, attn, S, S, D,
        (long long)S * D, (long long)S * D, (long long)S * S, 0.0625f, 0);

    // ---- softmax rows in place (fp32) + fp16 copy
    softmax_rows<<<Mtot, blk>>>(attn, ah);

    // ---- out = attn @ V = attn_h @ (V^T)^T  (fp16 out)
    gemm_h_nt<__half><<<dim3(D / 128, S / 128, 4), blk, GEMM_SMEM>>>(
        ah, vt, nullptr, t0, S, D, S,
        (long long)S * S, (long long)D * S, (long long)S * D, 1.0f, 0);

    // ---- MLP: three relu(linear) layers; last writes fp32 h output
    gemm_h_nt<__half><<<gLin, blk, GEMM_SMEM>>>(t0, wh + 3 * NW, b1, t1, Mtot, D, D, 0, 0, 0, 1.0f, 1);
    gemm_h_nt<__half><<<gLin, blk, GEMM_SMEM>>>(t1, wh + 4 * NW, b2, t0, Mtot, D, D, 0, 0, 0, 1.0f, 1);
    gemm_h_nt<float ><<<gLin, blk, GEMM_SMEM>>>(t0, wh + 5 * NW, b3, hout, Mtot, D, D, 0, 0, 0, 1.0f, 1);
}

// round 13
// speedup vs baseline: 4.0297x; 1.0849x over previous
#include <cuda_runtime.h>
#include <cuda_fp16.h>
#include <cstdint>
#include <cstddef>

// ---------------------------------------------------------------------------
// Problem constants: B=4, NQ=NK=4096, D=256
// d_out = [ h: 4*4096*256 | attn: 4*4096*4096 ]
// ---------------------------------------------------------------------------

// Scratch (device globals: allocation inside kernel_launch is forbidden)
__device__ __half g_xh [4 * 4096 * 256];
__device__ __half g_qh [4 * 4096 * 256];
__device__ __half g_q  [4 * 4096 * 256];
__device__ __half g_k  [4 * 4096 * 256];
__device__ __half g_vt [4 * 4096 * 256];   // V^T, written directly by V proj
__device__ __half g_t0 [4 * 4096 * 256];
__device__ __half g_t1 [4 * 4096 * 256];
__device__ __half g_w  [6][256 * 256];
__device__ __half g_ah [(size_t)4 * 4096 * 4096];   // fp16 scores, then attn

static __device__ __forceinline__ uint32_t smem_u32(const void* p) {
    uint32_t a;
    asm("{ .reg .u64 t; cvta.to.shared.u64 t, %1; cvt.u32.u64 %0, t; }"
        : "=r"(a) : "l"(p));
    return a;
}
static __device__ __forceinline__ uint32_t f2h2(float x, float y) {
    uint32_t r;
    asm("cvt.rn.f16x2.f32 %0, %1, %2;" : "=r"(r) : "f"(y), "f"(x));
    return r;
}
static __device__ __forceinline__ void cp16(uint32_t s, const void* g) {
    asm volatile("cp.async.cg.shared.global [%0], [%1], 16;" :: "r"(s), "l"(g));
}
#define CP_COMMIT() asm volatile("cp.async.commit_group;" ::: "memory")
#define CP_WAIT(n)  asm volatile("cp.async.wait_group %0;" :: "n"(n) : "memory")

// epilogue paired store: fp32 or fp16 destination
static __device__ __forceinline__ void store2(float* C, size_t idx, float x, float y) {
    *(float2*)(C + idx) = make_float2(x, y);
}
static __device__ __forceinline__ void store2(__half* C, size_t idx, float x, float y) {
    *(__half2*)(C + idx) = __floats2half2_rn(x, y);
}

// ===========================================================================
// HMMA fp16 NT GEMM core: C[M,N] = alpha * A[M,K] * B[N,K]^T (+bias, +relu)
//   fp16 operands in gmem (cp.async 16B direct to smem), fp32 accumulate.
//   CTA tile 128x128, BK=32; 3-stage circular cp.async pipeline, one
//   __syncthreads per chunk, prefetch distance 2.
//   8 warps = 2(m) x 4(n); warp tile 64x32.
//   Smem rows = 32 fp16 + 8 pad = 80B (5 x 16B): stride 5 mod 8 in 16B banks
//   -> conflict-free ldmatrix by construction.
//   transC=1 (V projection): writes C^T laid out as [batch][N=256][4096].
//   Requires M%128==0, N%128==0, K%32==0.
// ===========================================================================
#define H_ROW   40                   // fp16 per smem row (32 data + 8 pad)
#define H_MAT   (128 * H_ROW)        // 5120 halfs = 10240 B per matrix
#define STAGE_B (2 * H_MAT * 2)      // A+B bytes per stage = 20480
#define NSTAGE  3
#define GEMM_SMEM (NSTAGE * STAGE_B) // 61440 B dynamic

template <typename TOut>
static __device__ __forceinline__ void gemm_core(
    const __half* __restrict__ A, const __half* __restrict__ B,
    const float* __restrict__ bias, TOut* __restrict__ C,
    int M, int N, int K, float alpha, int relu, int transC, __half* smd)
{
    const int m0 = blockIdx.y * 128;
    const int n0 = blockIdx.x * 128;
    const int tid = threadIdx.x;
    const int w = tid >> 5;
    const int l = tid & 31;

    // ---- async loader mapping: row w*16+(l&15), 16B-chunks {2*(l>>4), +1}
    const int lrow = w * 16 + (l & 15);
    const int lc   = (l >> 4) * 2;
    const uint32_t smem_base = smem_u32(smd);
    const uint32_t sa = smem_base + (uint32_t)(lrow * 80 + lc * 16);
    const uint32_t sb = sa + (uint32_t)(H_MAT * 2);
    const __half* ag = A + (size_t)(m0 + lrow) * (size_t)K + lc * 8;
    const __half* bg = B + (size_t)(n0 + lrow) * (size_t)K + lc * 8;

    auto copy_chunk = [&](int c, int st) {
        const uint32_t off = (uint32_t)st * STAGE_B;
        const __half* a = ag + c * 32;
        const __half* b = bg + c * 32;
        cp16(sa + off, a);      cp16(sa + off + 16, a + 8);
        cp16(sb + off, b);      cp16(sb + off + 16, b + 8);
    };

    // ---- compute mapping
    const int wm = (w & 1) * 64;
    const int wn = (w >> 1) * 32;
    const uint32_t aoff = (uint32_t)((wm + (l & 15)) * 80 + (l >> 4) * 16);
    const uint32_t boff = (uint32_t)((wn + (l & 7)) * 80 + ((l >> 3) & 1) * 16);

    float acc[4][4][4];
#pragma unroll
    for (int i = 0; i < 4; i++)
#pragma unroll
        for (int j = 0; j < 4; j++)
#pragma unroll
            for (int q = 0; q < 4; q++) acc[i][j][q] = 0.0f;

    const int nch = K / 32;

    // prologue: stages 0,1 <- chunks 0,1
    copy_chunk(0, 0); CP_COMMIT();
    copy_chunk(1, 1); CP_COMMIT();

    int st_cmp = 0;
    int st_cpy = 2;
    for (int c = 0; c < nch; c++) {
        CP_WAIT(1);
        __syncthreads();

        if (c + 2 < nch) copy_chunk(c + 2, st_cpy);
        CP_COMMIT();

        const uint32_t aB = smem_base + (uint32_t)st_cmp * STAGE_B;
        const uint32_t bB = aB + (uint32_t)(H_MAT * 2);
#pragma unroll
        for (int s = 0; s < 2; s++) {
            uint32_t af[4][4];
#pragma unroll
            for (int ma = 0; ma < 4; ma++) {
                const uint32_t addr = aB + aoff + (uint32_t)(ma * 16 * 80 + s * 32);
                asm volatile(
                    "ldmatrix.sync.aligned.m8n8.x4.shared.b16 {%0,%1,%2,%3}, [%4];"
                    : "=r"(af[ma][0]), "=r"(af[ma][1]),
                      "=r"(af[ma][2]), "=r"(af[ma][3])
                    : "r"(addr));
            }
            uint32_t bf[4][2];
#pragma unroll
            for (int na = 0; na < 4; na++) {
                const uint32_t addr = bB + boff + (uint32_t)(na * 8 * 80 + s * 32);
                asm volatile(
                    "ldmatrix.sync.aligned.m8n8.x2.shared.b16 {%0,%1}, [%2];"
                    : "=r"(bf[na][0]), "=r"(bf[na][1])
                    : "r"(addr));
            }
#pragma unroll
            for (int ma = 0; ma < 4; ma++)
#pragma unroll
                for (int na = 0; na < 4; na++) {
                    asm volatile(
                        "mma.sync.aligned.m16n8k16.row.col.f32.f16.f16.f32 "
                        "{%0,%1,%2,%3}, {%4,%5,%6,%7}, {%8,%9}, {%0,%1,%2,%3};"
                        : "+f"(acc[ma][na][0]), "+f"(acc[ma][na][1]),
                          "+f"(acc[ma][na][2]), "+f"(acc[ma][na][3])
                        : "r"(af[ma][0]), "r"(af[ma][1]),
                          "r"(af[ma][2]), "r"(af[ma][3]),
                          "r"(bf[na][0]), "r"(bf[na][1]));
                }
        }
        st_cmp = (st_cmp == NSTAGE - 1) ? 0 : st_cmp + 1;
        st_cpy = (st_cpy == NSTAGE - 1) ? 0 : st_cpy + 1;
    }

    // ---- epilogue
    const int erow = m0 + wm + (l >> 2);
    const int ecol = n0 + wn + (l & 3) * 2;
#pragma unroll
    for (int ma = 0; ma < 4; ma++) {
        const int r = erow + ma * 16;
#pragma unroll
        for (int na = 0; na < 4; na++) {
            const int cc = ecol + na * 8;
            float2 bb = make_float2(0.f, 0.f);
            if (bias) bb = *(const float2*)(bias + cc);
            float lx = alpha * acc[ma][na][0] + bb.x;
            float ly = alpha * acc[ma][na][1] + bb.y;
            float hx = alpha * acc[ma][na][2] + bb.x;
            float hy = alpha * acc[ma][na][3] + bb.y;
            if (relu) {
                lx = fmaxf(lx, 0.f); ly = fmaxf(ly, 0.f);
                hx = fmaxf(hx, 0.f); hy = fmaxf(hy, 0.f);
            }
            if (!transC) {
                store2(C, (size_t)r * (size_t)N + cc, lx, ly);
                store2(C, (size_t)(r + 8) * (size_t)N + cc, hx, hy);
            } else {
                // C^T layout [batch][N][4096]; rows r are (b*4096 + t)
                const size_t b0 = ((size_t)(r >> 12) * 256 + cc) * 4096 + (r & 4095);
                C[b0]        = (TOut)lx;
                C[b0 + 4096] = (TOut)ly;
                const int r8 = r + 8;
                const size_t b1 = ((size_t)(r8 >> 12) * 256 + cc) * 4096 + (r8 & 4095);
                C[b1]        = (TOut)hx;
                C[b1 + 4096] = (TOut)hy;
            }
        }
    }
}

// Generic batched GEMM kernel (QK^T, AV, MLP layers)
template <typename TOut>
__global__ void __launch_bounds__(256, 2) gemm_h_nt(
    const __half* __restrict__ A, const __half* __restrict__ B,
    const float* __restrict__ bias, TOut* __restrict__ C,
    int M, int N, int K,
    long long sA, long long sB, long long sC,
    float alpha, int relu)
{
    extern __shared__ __align__(16) __half smd[];
    A += (size_t)blockIdx.z * (size_t)sA;
    B += (size_t)blockIdx.z * (size_t)sB;
    C += (size_t)blockIdx.z * (size_t)sC;
    gemm_core<TOut>(A, B, bias, C, M, N, K, alpha, relu, 0, smd);
}

// Fused q/k/v projections: grid.z selects {q, k, v}; v written transposed.
__global__ void __launch_bounds__(256, 2) qkv_proj(
    const __half* __restrict__ qh, const __half* __restrict__ xh,
    const __half* __restrict__ wh,
    const float* __restrict__ bq, const float* __restrict__ bk,
    const float* __restrict__ bv,
    __half* __restrict__ q, __half* __restrict__ k, __half* __restrict__ vt)
{
    extern __shared__ __align__(16) __half smd[];
    const int z = blockIdx.z;
    const __half* A = (z == 0) ? qh : xh;
    const __half* W = wh + z * 65536;
    const float* bias = (z == 0) ? bq : (z == 1) ? bk : bv;
    __half* C = (z == 0) ? q : (z == 1) ? k : vt;
    gemm_core<__half>(A, W, bias, C, 16384, 256, 256, 1.0f, 0, z == 2, smd);
}

// ===========================================================================
// One-shot fp32 -> fp16 conversion of query, x, and the 6 weights.
// Segments (in 8-elem units): query 524288 | x 524288 | 6 x 8192
// ===========================================================================
__global__ void __launch_bounds__(256) f2h_all(
    const float* __restrict__ query, const float* __restrict__ x,
    const float* __restrict__ Wq, const float* __restrict__ Wk,
    const float* __restrict__ Wv, const float* __restrict__ W1,
    const float* __restrict__ W2, const float* __restrict__ W3,
    __half* __restrict__ qh, __half* __restrict__ xh, __half* __restrict__ wh)
{
    const int idx = blockIdx.x * 256 + threadIdx.x;    // vec8 index
    const float* s;
    __half* d;
    int off;
    if (idx < 524288)            { s = query; d = qh; off = idx; }
    else if (idx < 1048576)      { s = x;     d = xh; off = idx - 524288; }
    else {
        const int wv8 = idx - 1048576;                 // 0 .. 49151
        const int wi = wv8 >> 13;                      // weight id 0..5
        off = wv8 & 8191;
        switch (wi) {
            case 0: s = Wq; break;  case 1: s = Wk; break;
            case 2: s = Wv; break;  case 3: s = W1; break;
            case 4: s = W2; break;  default: s = W3; break;
        }
        d = wh + wi * 65536;
    }
    const int i = off * 8;
    float4 u = *(const float4*)(s + i);
    float4 v = *(const float4*)(s + i + 4);
    uint4 o;
    o.x = f2h2(u.x, u.y); o.y = f2h2(u.z, u.w);
    o.z = f2h2(v.x, v.y); o.w = f2h2(v.z, v.w);
    *(uint4*)(d + i) = o;
}

// ---------------------------------------------------------------------------
// Row softmax: reads fp16 scores from ah, writes fp32 attn (output slot) and
// fp16 attn back into ah (for AV). attn[16384][4096].
// ---------------------------------------------------------------------------
static __device__ __forceinline__ float warpMax(float v) {
#pragma unroll
    for (int o = 16; o > 0; o >>= 1) v = fmaxf(v, __shfl_xor_sync(0xffffffffu, v, o));
    return v;
}
static __device__ __forceinline__ float warpSum(float v) {
#pragma unroll
    for (int o = 16; o > 0; o >>= 1) v += __shfl_xor_sync(0xffffffffu, v, o);
    return v;
}

__global__ void __launch_bounds__(256) softmax_rows(
    float* __restrict__ attn, __half* __restrict__ ah)
{
    __shared__ float red[8];
    __shared__ float bcast;
    const size_t row = blockIdx.x;
    float* p = attn + row * 4096;
    __half2* ph = (__half2*)(ah + row * 4096);
    const int tid = threadIdx.x;

    float v[16];
#pragma unroll
    for (int j = 0; j < 8; j++) {
        const float2 f = __half22float2(ph[tid + j * 256]);
        v[2 * j]     = f.x;
        v[2 * j + 1] = f.y;
    }

    float m = v[0];
#pragma unroll
    for (int i = 1; i < 16; i++) m = fmaxf(m, v[i]);
    m = warpMax(m);
    if ((tid & 31) == 0) red[tid >> 5] = m;
    __syncthreads();
    if (tid < 32) {
        float t = (tid < 8) ? red[tid] : -3.4e38f;
        t = warpMax(t);
        if (tid == 0) bcast = t;
    }
    __syncthreads();
    m = bcast;

    float s = 0.0f;
#pragma unroll
    for (int i = 0; i < 16; i++) { v[i] = __expf(v[i] - m); s += v[i]; }
    s = warpSum(s);
    __syncthreads();
    if ((tid & 31) == 0) red[tid >> 5] = s;
    __syncthreads();
    if (tid < 32) {
        float t = (tid < 8) ? red[tid] : 0.0f;
        t = warpSum(t);
        if (tid == 0) bcast = t;
    }
    __syncthreads();
    const float inv = 1.0f / bcast;
#pragma unroll
    for (int j = 0; j < 8; j++) {
        const float r0 = v[2 * j] * inv;
        const float r1 = v[2 * j + 1] * inv;
        *(float2*)(p + 2 * (tid + j * 256)) = make_float2(r0, r1);
        ph[tid + j * 256] = __floats2half2_rn(r0, r1);
    }
}

// ---------------------------------------------------------------------------
// Host launcher (graph-capturable: kernel launches only)
// ---------------------------------------------------------------------------
extern "C" void kernel_launch(void* const* d_in, const int* in_sizes, int n_in,
                              void* d_out, int out_size)
{
    (void)in_sizes; (void)n_in; (void)out_size;
    const float* x     = (const float*)d_in[0];
    const float* query = (const float*)d_in[1];
    const float* Wq = (const float*)d_in[2];  const float* bq = (const float*)d_in[3];
    const float* Wk = (const float*)d_in[4];  const float* bk = (const float*)d_in[5];
    const float* Wv = (const float*)d_in[6];  const float* bv = (const float*)d_in[7];
    const float* W1 = (const float*)d_in[8];  const float* b1 = (const float*)d_in[9];
    const float* W2 = (const float*)d_in[10]; const float* b2 = (const float*)d_in[11];
    const float* W3 = (const float*)d_in[12]; const float* b3 = (const float*)d_in[13];

    float* outp = (float*)d_out;
    float* hout = outp;                                    // [4,4096,256]
    float* attn = outp + (size_t)4 * 4096 * 256;           // [4,4096,4096]

    __half *xh, *qh, *q, *k, *vt, *t0, *t1, *wh, *ah;
    cudaGetSymbolAddress((void**)&xh, g_xh);
    cudaGetSymbolAddress((void**)&qh, g_qh);
    cudaGetSymbolAddress((void**)&q,  g_q);
    cudaGetSymbolAddress((void**)&k,  g_k);
    cudaGetSymbolAddress((void**)&vt, g_vt);
    cudaGetSymbolAddress((void**)&t0, g_t0);
    cudaGetSymbolAddress((void**)&t1, g_t1);
    cudaGetSymbolAddress((void**)&wh, g_w);
    cudaGetSymbolAddress((void**)&ah, g_ah);

    cudaFuncSetAttribute(gemm_h_nt<__half>,
                         cudaFuncAttributeMaxDynamicSharedMemorySize, GEMM_SMEM);
    cudaFuncSetAttribute(gemm_h_nt<float>,
                         cudaFuncAttributeMaxDynamicSharedMemorySize, GEMM_SMEM);
    cudaFuncSetAttribute(qkv_proj,
                         cudaFuncAttributeMaxDynamicSharedMemorySize, GEMM_SMEM);

    const int Mtot = 4 * 4096;
    const int D = 256;
    const int S = 4096;
    const dim3 blk(256);
    const dim3 gLin(D / 128, Mtot / 128, 1);    // (2, 128, 1)

    // ---- one-shot fp32 -> fp16 conversions (query, x, 6 weights)
    f2h_all<<<4288, 256>>>(query, x, Wq, Wk, Wv, W1, W2, W3, qh, xh, wh);

    // ---- fused q/k/v projections; V written transposed into vt
    qkv_proj<<<dim3(2, 128, 3), blk, GEMM_SMEM>>>(qh, xh, wh, bq, bk, bv, q, k, vt);

    // ---- scores = (q @ k^T) / sqrt(D) -> fp16 into ah
    gemm_h_nt<__half><<<dim3(S / 128, S / 128, 4), blk, GEMM_SMEM>>>(
        q, k, nullptr, ah, S, S, D,
        (long long)S * D, (long long)S * D, (long long)S * S, 0.0625f, 0);

    // ---- softmax: fp16 scores -> fp32 attn output + fp16 attn (in ah)
    softmax_rows<<<Mtot, blk>>>(attn, ah);

    // ---- out = attn @ V = attn_h @ (V^T)^T  (fp16 out)
    gemm_h_nt<__half><<<dim3(D / 128, S / 128, 4), blk, GEMM_SMEM>>>(
        ah, vt, nullptr, t0, S, D, S,
        (long long)S * S, (long long)D * S, (long long)S * D, 1.0f, 0);

    // ---- MLP: three relu(linear) layers; last writes fp32 h output
    gemm_h_nt<__half><<<gLin, blk, GEMM_SMEM>>>(t0, wh + 3 * 65536, b1, t1, Mtot, D, D, 0, 0, 0, 1.0f, 1);
    gemm_h_nt<__half><<<gLin, blk, GEMM_SMEM>>>(t1, wh + 4 * 65536, b2, t0, Mtot, D, D, 0, 0, 0, 1.0f, 1);
    gemm_h_nt<float ><<<gLin, blk, GEMM_SMEM>>>(t0, wh + 5 * 65536, b3, hout, Mtot, D, D, 0, 0, 0, 1.0f, 1);
}